// round 1
// baseline (speedup 1.0000x reference)
#include <cuda_runtime.h>
#include <math.h>

// ---------------------------------------------------------------------------
// Problem constants
// ---------------------------------------------------------------------------
#define TOKENS 4096        // B*S = 2*2048
#define DMODEL 1024
#define DFF    4096
#define NHEADS 16
#define DK     64
#define SEQ    2048

// ---------------------------------------------------------------------------
// Scratch (device globals: no allocation allowed in kernel_launch)
// ---------------------------------------------------------------------------
__device__ float g_q   [TOKENS * DMODEL];
__device__ float g_k   [TOKENS * DMODEL];
__device__ float g_v   [TOKENS * DMODEL];
__device__ float g_attn[TOKENS * DMODEL];
__device__ float g_proj[TOKENS * DMODEL];
__device__ float g_x1  [TOKENS * DMODEL];
__device__ float g_ff  [TOKENS * DFF];

// ---------------------------------------------------------------------------
// GEMM:  C[M,N] = A[M,K] @ B[N,K]^T   (nn.Linear layout; both K-major)
// 128x128 block tile, BK=16, 256 threads, 8x8 per-thread register tile.
// EPI: 0 = none, 1 = exact GELU
// ---------------------------------------------------------------------------
template <int EPI>
__global__ __launch_bounds__(256)
void gemm_nt(const float* __restrict__ A, const float* __restrict__ B,
             float* __restrict__ C, int M, int N, int K)
{
    __shared__ float As[16][128];   // [k][m]
    __shared__ float Bs[16][128];   // [k][n]

    const int tid = threadIdx.x;
    const int tx  = tid & 15;       // 0..15 -> n
    const int ty  = tid >> 4;       // 0..15 -> m
    const int bm  = blockIdx.y * 128;
    const int bn  = blockIdx.x * 128;

    float acc[8][8];
#pragma unroll
    for (int i = 0; i < 8; i++)
#pragma unroll
        for (int j = 0; j < 8; j++) acc[i][j] = 0.f;

    for (int kt = 0; kt < K; kt += 16) {
        // load A tile (128x16) and B tile (128x16), store transposed
#pragma unroll
        for (int it = 0; it < 2; it++) {
            int f   = tid + it * 256;       // 0..511 float4 slots
            int row = f >> 2;               // 0..127
            int col = (f & 3) << 2;         // 0,4,8,12
            float4 va = *(const float4*)(A + (size_t)(bm + row) * K + kt + col);
            As[col + 0][row] = va.x;
            As[col + 1][row] = va.y;
            As[col + 2][row] = va.z;
            As[col + 3][row] = va.w;
            float4 vb = *(const float4*)(B + (size_t)(bn + row) * K + kt + col);
            Bs[col + 0][row] = vb.x;
            Bs[col + 1][row] = vb.y;
            Bs[col + 2][row] = vb.z;
            Bs[col + 3][row] = vb.w;
        }
        __syncthreads();

#pragma unroll
        for (int kk = 0; kk < 16; kk++) {
            float a[8], b[8];
            *(float4*)(a)     = *(const float4*)&As[kk][ty * 8];
            *(float4*)(a + 4) = *(const float4*)&As[kk][ty * 8 + 4];
            *(float4*)(b)     = *(const float4*)&Bs[kk][tx * 8];
            *(float4*)(b + 4) = *(const float4*)&Bs[kk][tx * 8 + 4];
#pragma unroll
            for (int i = 0; i < 8; i++)
#pragma unroll
                for (int j = 0; j < 8; j++)
                    acc[i][j] = fmaf(a[i], b[j], acc[i][j]);
        }
        __syncthreads();
    }

    // epilogue + store
#pragma unroll
    for (int i = 0; i < 8; i++) {
        float out[8];
#pragma unroll
        for (int j = 0; j < 8; j++) {
            float v = acc[i][j];
            if (EPI == 1) v = 0.5f * v * (1.f + erff(v * 0.70710678118654752f));
            out[j] = v;
        }
        float* cp = C + (size_t)(bm + ty * 8 + i) * N + bn + tx * 8;
        *(float4*)(cp)     = *(float4*)(out);
        *(float4*)(cp + 4) = *(float4*)(out + 4);
    }
}

// ---------------------------------------------------------------------------
// Flash attention (fp32, Dk=64). One block = 64-query tile of one (b,h).
// 128 threads: r = tid/8 (query group of 4), c = tid%8 (8 dims/keys group).
// Q,K,V,O are the [TOKENS, DMODEL] projection buffers; head h occupies
// columns [h*64, h*64+64).
// ---------------------------------------------------------------------------
__global__ __launch_bounds__(128)
void flash_attn(const float* __restrict__ Q, const float* __restrict__ K,
                const float* __restrict__ V, float* __restrict__ O)
{
    __shared__ float Qs[64 * 64];   // [kk][q]  (transposed)
    __shared__ float Ks[64 * 64];   // [kk][key] -> reused as Ps [key][q]
    __shared__ float Vs[64 * 64];   // [key][d]

    const int bh = blockIdx.y;
    const int b  = bh >> 4;
    const int h  = bh & 15;
    const int q0 = blockIdx.x * 64;
    const int tid = threadIdx.x;
    const int r = tid >> 3;         // 0..15
    const int c = tid & 7;          // 0..7

    const size_t base = (size_t)b * SEQ * DMODEL + h * DK;
    const float* Qb = Q + base;
    const float* Kb = K + base;
    const float* Vb = V + base;
    float*       Ob = O + base;

    // load Q tile (scaled by 1/sqrt(Dk)), transposed [kk][q]
    for (int f = tid; f < 64 * 16; f += 128) {
        int row = f >> 4;
        int col = (f & 15) << 2;
        float4 v = *(const float4*)(Qb + (size_t)(q0 + row) * DMODEL + col);
        Qs[(col + 0) * 64 + row] = v.x * 0.125f;
        Qs[(col + 1) * 64 + row] = v.y * 0.125f;
        Qs[(col + 2) * 64 + row] = v.z * 0.125f;
        Qs[(col + 3) * 64 + row] = v.w * 0.125f;
    }

    float m[4], l[4], o[4][8];
#pragma unroll
    for (int i = 0; i < 4; i++) {
        m[i] = -1e30f; l[i] = 0.f;
#pragma unroll
        for (int j = 0; j < 8; j++) o[i][j] = 0.f;
    }

    for (int kt = 0; kt < SEQ / 64; kt++) {
        const int k0 = kt * 64;
        __syncthreads();    // prior O-update done reading Ks/Vs; Q visible after next sync

        // load K (transposed [kk][key]) and V (natural [key][d])
        for (int f = tid; f < 64 * 16; f += 128) {
            int row = f >> 4;
            int col = (f & 15) << 2;
            float4 kv = *(const float4*)(Kb + (size_t)(k0 + row) * DMODEL + col);
            Ks[(col + 0) * 64 + row] = kv.x;
            Ks[(col + 1) * 64 + row] = kv.y;
            Ks[(col + 2) * 64 + row] = kv.z;
            Ks[(col + 3) * 64 + row] = kv.w;
            float4 vv = *(const float4*)(Vb + (size_t)(k0 + row) * DMODEL + col);
            *(float4*)&Vs[row * 64 + col] = vv;
        }
        __syncthreads();

        // S = (Q * scale) @ K^T : thread owns 4 queries x 8 keys
        float s[4][8];
#pragma unroll
        for (int i = 0; i < 4; i++)
#pragma unroll
            for (int j = 0; j < 8; j++) s[i][j] = 0.f;

#pragma unroll 8
        for (int kk = 0; kk < 64; kk++) {
            float a[4], bb[8];
#pragma unroll
            for (int i = 0; i < 4; i++) a[i] = Qs[kk * 64 + r * 4 + i];
#pragma unroll
            for (int j = 0; j < 8; j++) bb[j] = Ks[kk * 64 + c * 8 + j];
#pragma unroll
            for (int i = 0; i < 4; i++)
#pragma unroll
                for (int j = 0; j < 8; j++)
                    s[i][j] = fmaf(a[i], bb[j], s[i][j]);
        }

        // online softmax (row stats reduced over the 8 c-threads)
        float p[4][8], alpha[4];
#pragma unroll
        for (int i = 0; i < 4; i++) {
            float tmax = s[i][0];
#pragma unroll
            for (int j = 1; j < 8; j++) tmax = fmaxf(tmax, s[i][j]);
            tmax = fmaxf(tmax, __shfl_xor_sync(0xffffffffu, tmax, 1));
            tmax = fmaxf(tmax, __shfl_xor_sync(0xffffffffu, tmax, 2));
            tmax = fmaxf(tmax, __shfl_xor_sync(0xffffffffu, tmax, 4));
            float mn = fmaxf(m[i], tmax);
            alpha[i] = __expf(m[i] - mn);
            float sum = 0.f;
#pragma unroll
            for (int j = 0; j < 8; j++) {
                p[i][j] = __expf(s[i][j] - mn);
                sum += p[i][j];
            }
            sum += __shfl_xor_sync(0xffffffffu, sum, 1);
            sum += __shfl_xor_sync(0xffffffffu, sum, 2);
            sum += __shfl_xor_sync(0xffffffffu, sum, 4);
            l[i] = l[i] * alpha[i] + sum;
            m[i] = mn;
#pragma unroll
            for (int j = 0; j < 8; j++) o[i][j] *= alpha[i];
        }

        __syncthreads();    // all threads done reading Ks
        // write P transposed [key][q] into Ks storage
#pragma unroll
        for (int j = 0; j < 8; j++)
#pragma unroll
            for (int i = 0; i < 4; i++)
                Ks[(c * 8 + j) * 64 + (r * 4 + i)] = p[i][j];
        __syncthreads();

        // O += P @ V : thread owns 4 queries x 8 dims (d = c*8..)
#pragma unroll 8
        for (int key = 0; key < 64; key++) {
            float pv[4], vv[8];
#pragma unroll
            for (int i = 0; i < 4; i++) pv[i] = Ks[key * 64 + r * 4 + i];
#pragma unroll
            for (int j = 0; j < 8; j++) vv[j] = Vs[key * 64 + c * 8 + j];
#pragma unroll
            for (int i = 0; i < 4; i++)
#pragma unroll
                for (int j = 0; j < 8; j++)
                    o[i][j] = fmaf(pv[i], vv[j], o[i][j]);
        }
    }

    // epilogue: O / l
#pragma unroll
    for (int i = 0; i < 4; i++) {
        float inv = 1.f / l[i];
        float out[8];
#pragma unroll
        for (int j = 0; j < 8; j++) out[j] = o[i][j] * inv;
        float* op = Ob + (size_t)(q0 + r * 4 + i) * DMODEL + c * 8;
        *(float4*)(op)     = *(float4*)(out);
        *(float4*)(op + 4) = *(float4*)(out + 4);
    }
}

// ---------------------------------------------------------------------------
// y = LayerNorm(a + b) * gamma + beta   (row = token, D = 1024)
// 256 threads, 4 floats each.
// ---------------------------------------------------------------------------
__global__ __launch_bounds__(256)
void add_ln(const float* __restrict__ a, const float* __restrict__ b,
            const float* __restrict__ gamma, const float* __restrict__ beta,
            float* __restrict__ y)
{
    const int row = blockIdx.x;
    const int tid = threadIdx.x;
    __shared__ float rs[256], rq[256];

    float4 va = ((const float4*)(a + (size_t)row * DMODEL))[tid];
    float4 vb = ((const float4*)(b + (size_t)row * DMODEL))[tid];
    float s0 = va.x + vb.x, s1 = va.y + vb.y, s2 = va.z + vb.z, s3 = va.w + vb.w;

    rs[tid] = s0 + s1 + s2 + s3;
    rq[tid] = s0 * s0 + s1 * s1 + s2 * s2 + s3 * s3;
    __syncthreads();
#pragma unroll
    for (int off = 128; off > 0; off >>= 1) {
        if (tid < off) { rs[tid] += rs[tid + off]; rq[tid] += rq[tid + off]; }
        __syncthreads();
    }
    const float mu   = rs[0] * (1.f / DMODEL);
    const float var  = rq[0] * (1.f / DMODEL) - mu * mu;
    const float rinv = rsqrtf(var + 1e-5f);

    float4 g = ((const float4*)gamma)[tid];
    float4 be = ((const float4*)beta)[tid];
    float4 out;
    out.x = (s0 - mu) * rinv * g.x + be.x;
    out.y = (s1 - mu) * rinv * g.y + be.y;
    out.z = (s2 - mu) * rinv * g.z + be.z;
    out.w = (s3 - mu) * rinv * g.w + be.w;
    ((float4*)(y + (size_t)row * DMODEL))[tid] = out;
}

// ---------------------------------------------------------------------------
// launch
// ---------------------------------------------------------------------------
extern "C" void kernel_launch(void* const* d_in, const int* in_sizes, int n_in,
                              void* d_out, int out_size)
{
    const float* x  = (const float*)d_in[0];
    const float* Wq = (const float*)d_in[1];
    const float* Wk = (const float*)d_in[2];
    const float* Wv = (const float*)d_in[3];
    const float* Wo = (const float*)d_in[4];
    const float* W1 = (const float*)d_in[5];
    const float* W2 = (const float*)d_in[6];
    const float* g1 = (const float*)d_in[7];
    const float* b1 = (const float*)d_in[8];
    const float* g2 = (const float*)d_in[9];
    const float* b2 = (const float*)d_in[10];
    float* out = (float*)d_out;

    float *q, *k, *v, *attn, *proj, *x1, *ff;
    cudaGetSymbolAddress((void**)&q,    g_q);
    cudaGetSymbolAddress((void**)&k,    g_k);
    cudaGetSymbolAddress((void**)&v,    g_v);
    cudaGetSymbolAddress((void**)&attn, g_attn);
    cudaGetSymbolAddress((void**)&proj, g_proj);
    cudaGetSymbolAddress((void**)&x1,   g_x1);
    cudaGetSymbolAddress((void**)&ff,   g_ff);

    dim3 blk(256);

    // QKV projections
    dim3 gqkv(DMODEL / 128, TOKENS / 128);
    gemm_nt<0><<<gqkv, blk>>>(x, Wq, q, TOKENS, DMODEL, DMODEL);
    gemm_nt<0><<<gqkv, blk>>>(x, Wk, k, TOKENS, DMODEL, DMODEL);
    gemm_nt<0><<<gqkv, blk>>>(x, Wv, v, TOKENS, DMODEL, DMODEL);

    // attention
    dim3 gattn(SEQ / 64, 2 * NHEADS);
    flash_attn<<<gattn, dim3(128)>>>(q, k, v, attn);

    // output projection + residual + LN1
    gemm_nt<0><<<gqkv, blk>>>(attn, Wo, proj, TOKENS, DMODEL, DMODEL);
    add_ln<<<TOKENS, 256>>>(x, proj, g1, b1, x1);

    // FF1 (+GELU), FF2, residual + LN2
    dim3 gff1(DFF / 128, TOKENS / 128);
    gemm_nt<1><<<gff1, blk>>>(x1, W1, ff, TOKENS, DFF, DMODEL);
    gemm_nt<0><<<gqkv, blk>>>(ff, W2, proj, TOKENS, DMODEL, DFF);
    add_ln<<<TOKENS, 256>>>(x1, proj, g2, b2, out);
}

// round 3
// speedup vs baseline: 1.7909x; 1.7909x over previous
#include <cuda_runtime.h>
#include <math.h>
#include <cstdint>

// ---------------------------------------------------------------------------
// Problem constants
// ---------------------------------------------------------------------------
#define TOKENS 4096        // B*S = 2*2048
#define DMODEL 1024
#define DFF    4096
#define NHEADS 16
#define DK     64
#define SEQ    2048

// ---------------------------------------------------------------------------
// Scratch (device globals: no allocation allowed in kernel_launch)
// ---------------------------------------------------------------------------
__device__ float g_q   [TOKENS * DMODEL];
__device__ float g_k   [TOKENS * DMODEL];
__device__ float g_v   [TOKENS * DMODEL];
__device__ float g_attn[TOKENS * DMODEL];
__device__ float g_proj[TOKENS * DMODEL];
__device__ float g_x1  [TOKENS * DMODEL];
__device__ float g_ff  [TOKENS * DFF];

// ---------------------------------------------------------------------------
// Helpers
// ---------------------------------------------------------------------------
__device__ __forceinline__ uint32_t smem_u32(const void* p) {
    uint32_t a;
    asm("{ .reg .u64 t; cvta.to.shared.u64 t, %1; cvt.u32.u64 %0, t; }"
        : "=r"(a) : "l"(p));
    return a;
}

#define CP_ASYNC16(dst_u32, src_ptr) \
    asm volatile("cp.async.cg.shared.global [%0], [%1], 16;" \
        :: "r"(dst_u32), "l"(src_ptr))
#define CP_COMMIT() asm volatile("cp.async.commit_group;")
#define CP_WAIT(n)  asm volatile("cp.async.wait_group %0;" :: "n"(n))

// m16n8k8 tf32 HMMA, fp32 accumulate. a: 4 regs, b: 2 regs, c: 4 floats.
#define MMA_TF32(c, a, b) \
    asm volatile("mma.sync.aligned.m16n8k8.row.col.f32.tf32.tf32.f32 " \
        "{%0,%1,%2,%3}, {%4,%5,%6,%7}, {%8,%9}, {%0,%1,%2,%3};" \
        : "+f"((c)[0]), "+f"((c)[1]), "+f"((c)[2]), "+f"((c)[3]) \
        : "r"((a)[0]), "r"((a)[1]), "r"((a)[2]), "r"((a)[3]), \
          "r"((b)[0]), "r"((b)[1]))

// ---------------------------------------------------------------------------
// tf32 mma.sync GEMM:  C[M,N] = A[M,K] @ B[N,K]^T   (nn.Linear layout)
// Tile 128x128, BK=32, 256 threads (8 warps: 2 m x 4 n, 64x32 each),
// cp.async double-buffered SMEM, padded rows (36 floats) for conflict-free
// fragment loads. EPI: 0 = none, 1 = exact GELU.
// ---------------------------------------------------------------------------
#define LDPAD    36                    // 32 + 4 floats: bank = 4*(l>>2)+(l&3)
#define TILE_F   (128 * LDPAD)         // floats per operand tile buffer
#define GEMM_SMEM (4 * TILE_F * 4)     // A0,A1,B0,B1 -> 73728 B

template <int EPI>
__global__ __launch_bounds__(256)
void gemm_mma(const float* __restrict__ A, const float* __restrict__ B,
              float* __restrict__ C, int M, int N, int K)
{
    extern __shared__ float smem[];
    float* sA[2] = { smem,            smem + TILE_F };
    float* sB[2] = { smem + 2*TILE_F, smem + 3*TILE_F };
    const uint32_t sA_u[2] = { smem_u32(sA[0]), smem_u32(sA[1]) };
    const uint32_t sB_u[2] = { smem_u32(sB[0]), smem_u32(sB[1]) };

    const int tid = threadIdx.x;
    const int wid = tid >> 5;
    const int lid = tid & 31;
    const int gid = lid >> 2;          // 0..7
    const int tig = lid & 3;           // 0..3
    const int wm0 = (wid & 1) * 64;    // warp m offset in tile
    const int wn0 = (wid >> 1) * 32;   // warp n offset in tile
    const int bm  = blockIdx.y * 128;
    const int bn  = blockIdx.x * 128;

    const int ldRow = tid >> 3;        // 0..31 (with it: 0..127)
    const int ldC4  = (tid & 7) << 2;  // 0,4,...,28

    const float* Ab = A + (size_t)bm * K;
    const float* Bb = B + (size_t)bn * K;

    float acc[4][4][4];
#pragma unroll
    for (int i = 0; i < 4; i++)
#pragma unroll
        for (int j = 0; j < 4; j++)
#pragma unroll
            for (int r = 0; r < 4; r++) acc[i][j][r] = 0.f;

    const int KT = K >> 5;             // BK = 32

    // --- tile loader (cp.async, 8 x 16B per thread) ---
    auto load_tile = [&](int kt, int buf) {
        const float* Ak = Ab + (size_t)kt * 32;
        const float* Bk = Bb + (size_t)kt * 32;
#pragma unroll
        for (int it = 0; it < 4; it++) {
            int row = ldRow + it * 32;
            uint32_t so = (uint32_t)(row * LDPAD + ldC4) * 4u;
            CP_ASYNC16(sA_u[buf] + so, Ak + (size_t)row * K + ldC4);
            CP_ASYNC16(sB_u[buf] + so, Bk + (size_t)row * K + ldC4);
        }
        CP_COMMIT();
    };

    load_tile(0, 0);

    for (int kt = 0; kt < KT; kt++) {
        const int buf = kt & 1;
        if (kt + 1 < KT) {
            load_tile(kt + 1, buf ^ 1);
            CP_WAIT(1);
        } else {
            CP_WAIT(0);
        }
        __syncthreads();

        const float* cA = sA[buf];
        const float* cB = sB[buf];
#pragma unroll
        for (int ks = 0; ks < 4; ks++) {
            const int k0 = ks * 8;
            uint32_t a[4][4], b[4][2];
#pragma unroll
            for (int fm = 0; fm < 4; fm++) {
                const float* p = cA + (wm0 + fm * 16 + gid) * LDPAD + k0 + tig;
                a[fm][0] = __float_as_uint(p[0]);
                a[fm][1] = __float_as_uint(p[8 * LDPAD]);
                a[fm][2] = __float_as_uint(p[4]);
                a[fm][3] = __float_as_uint(p[8 * LDPAD + 4]);
            }
#pragma unroll
            for (int fn = 0; fn < 4; fn++) {
                const float* p = cB + (wn0 + fn * 8 + gid) * LDPAD + k0 + tig;
                b[fn][0] = __float_as_uint(p[0]);
                b[fn][1] = __float_as_uint(p[4]);
            }
#pragma unroll
            for (int fm = 0; fm < 4; fm++)
#pragma unroll
                for (int fn = 0; fn < 4; fn++)
                    MMA_TF32(acc[fm][fn], a[fm], b[fn]);
        }
        __syncthreads();
    }

    // --- epilogue ---
#pragma unroll
    for (int fm = 0; fm < 4; fm++) {
#pragma unroll
        for (int fn = 0; fn < 4; fn++) {
            float v[4];
#pragma unroll
            for (int r = 0; r < 4; r++) {
                float t = acc[fm][fn][r];
                if (EPI == 1) t = 0.5f * t * (1.f + erff(t * 0.70710678118654752f));
                v[r] = t;
            }
            const int row0 = bm + wm0 + fm * 16 + gid;
            const int col  = bn + wn0 + fn * 8 + tig * 2;
            *(float2*)(C + (size_t)row0 * N + col)       = make_float2(v[0], v[1]);
            *(float2*)(C + (size_t)(row0 + 8) * N + col) = make_float2(v[2], v[3]);
        }
    }
}

// ---------------------------------------------------------------------------
// Flash attention (fp32, Dk=64) — unchanged.
// ---------------------------------------------------------------------------
__global__ __launch_bounds__(128)
void flash_attn(const float* __restrict__ Q, const float* __restrict__ K,
                const float* __restrict__ V, float* __restrict__ O)
{
    __shared__ float Qs[64 * 64];
    __shared__ float Ks[64 * 64];
    __shared__ float Vs[64 * 64];

    const int bh = blockIdx.y;
    const int b  = bh >> 4;
    const int h  = bh & 15;
    const int q0 = blockIdx.x * 64;
    const int tid = threadIdx.x;
    const int r = tid >> 3;
    const int c = tid & 7;

    const size_t base = (size_t)b * SEQ * DMODEL + h * DK;
    const float* Qb = Q + base;
    const float* Kb = K + base;
    const float* Vb = V + base;
    float*       Ob = O + base;

    for (int f = tid; f < 64 * 16; f += 128) {
        int row = f >> 4;
        int col = (f & 15) << 2;
        float4 v = *(const float4*)(Qb + (size_t)(q0 + row) * DMODEL + col);
        Qs[(col + 0) * 64 + row] = v.x * 0.125f;
        Qs[(col + 1) * 64 + row] = v.y * 0.125f;
        Qs[(col + 2) * 64 + row] = v.z * 0.125f;
        Qs[(col + 3) * 64 + row] = v.w * 0.125f;
    }

    float m[4], l[4], o[4][8];
#pragma unroll
    for (int i = 0; i < 4; i++) {
        m[i] = -1e30f; l[i] = 0.f;
#pragma unroll
        for (int j = 0; j < 8; j++) o[i][j] = 0.f;
    }

    for (int kt = 0; kt < SEQ / 64; kt++) {
        const int k0 = kt * 64;
        __syncthreads();

        for (int f = tid; f < 64 * 16; f += 128) {
            int row = f >> 4;
            int col = (f & 15) << 2;
            float4 kv = *(const float4*)(Kb + (size_t)(k0 + row) * DMODEL + col);
            Ks[(col + 0) * 64 + row] = kv.x;
            Ks[(col + 1) * 64 + row] = kv.y;
            Ks[(col + 2) * 64 + row] = kv.z;
            Ks[(col + 3) * 64 + row] = kv.w;
            float4 vv = *(const float4*)(Vb + (size_t)(k0 + row) * DMODEL + col);
            *(float4*)&Vs[row * 64 + col] = vv;
        }
        __syncthreads();

        float s[4][8];
#pragma unroll
        for (int i = 0; i < 4; i++)
#pragma unroll
            for (int j = 0; j < 8; j++) s[i][j] = 0.f;

#pragma unroll 8
        for (int kk = 0; kk < 64; kk++) {
            float a[4], bb[8];
#pragma unroll
            for (int i = 0; i < 4; i++) a[i] = Qs[kk * 64 + r * 4 + i];
#pragma unroll
            for (int j = 0; j < 8; j++) bb[j] = Ks[kk * 64 + c * 8 + j];
#pragma unroll
            for (int i = 0; i < 4; i++)
#pragma unroll
                for (int j = 0; j < 8; j++)
                    s[i][j] = fmaf(a[i], bb[j], s[i][j]);
        }

        float p[4][8], alpha[4];
#pragma unroll
        for (int i = 0; i < 4; i++) {
            float tmax = s[i][0];
#pragma unroll
            for (int j = 1; j < 8; j++) tmax = fmaxf(tmax, s[i][j]);
            tmax = fmaxf(tmax, __shfl_xor_sync(0xffffffffu, tmax, 1));
            tmax = fmaxf(tmax, __shfl_xor_sync(0xffffffffu, tmax, 2));
            tmax = fmaxf(tmax, __shfl_xor_sync(0xffffffffu, tmax, 4));
            float mn = fmaxf(m[i], tmax);
            alpha[i] = __expf(m[i] - mn);
            float sum = 0.f;
#pragma unroll
            for (int j = 0; j < 8; j++) {
                p[i][j] = __expf(s[i][j] - mn);
                sum += p[i][j];
            }
            sum += __shfl_xor_sync(0xffffffffu, sum, 1);
            sum += __shfl_xor_sync(0xffffffffu, sum, 2);
            sum += __shfl_xor_sync(0xffffffffu, sum, 4);
            l[i] = l[i] * alpha[i] + sum;
            m[i] = mn;
#pragma unroll
            for (int j = 0; j < 8; j++) o[i][j] *= alpha[i];
        }

        __syncthreads();
#pragma unroll
        for (int j = 0; j < 8; j++)
#pragma unroll
            for (int i = 0; i < 4; i++)
                Ks[(c * 8 + j) * 64 + (r * 4 + i)] = p[i][j];
        __syncthreads();

#pragma unroll 8
        for (int key = 0; key < 64; key++) {
            float pv[4], vv[8];
#pragma unroll
            for (int i = 0; i < 4; i++) pv[i] = Ks[key * 64 + r * 4 + i];
#pragma unroll
            for (int j = 0; j < 8; j++) vv[j] = Vs[key * 64 + c * 8 + j];
#pragma unroll
            for (int i = 0; i < 4; i++)
#pragma unroll
                for (int j = 0; j < 8; j++)
                    o[i][j] = fmaf(pv[i], vv[j], o[i][j]);
        }
    }

#pragma unroll
    for (int i = 0; i < 4; i++) {
        float inv = 1.f / l[i];
        float out[8];
#pragma unroll
        for (int j = 0; j < 8; j++) out[j] = o[i][j] * inv;
        float* op = Ob + (size_t)(q0 + r * 4 + i) * DMODEL + c * 8;
        *(float4*)(op)     = *(float4*)(out);
        *(float4*)(op + 4) = *(float4*)(out + 4);
    }
}

// ---------------------------------------------------------------------------
// y = LayerNorm(a + b) * gamma + beta
// ---------------------------------------------------------------------------
__global__ __launch_bounds__(256)
void add_ln(const float* __restrict__ a, const float* __restrict__ b,
            const float* __restrict__ gamma, const float* __restrict__ beta,
            float* __restrict__ y)
{
    const int row = blockIdx.x;
    const int tid = threadIdx.x;
    __shared__ float rs[256], rq[256];

    float4 va = ((const float4*)(a + (size_t)row * DMODEL))[tid];
    float4 vb = ((const float4*)(b + (size_t)row * DMODEL))[tid];
    float s0 = va.x + vb.x, s1 = va.y + vb.y, s2 = va.z + vb.z, s3 = va.w + vb.w;

    rs[tid] = s0 + s1 + s2 + s3;
    rq[tid] = s0 * s0 + s1 * s1 + s2 * s2 + s3 * s3;
    __syncthreads();
#pragma unroll
    for (int off = 128; off > 0; off >>= 1) {
        if (tid < off) { rs[tid] += rs[tid + off]; rq[tid] += rq[tid + off]; }
        __syncthreads();
    }
    const float mu   = rs[0] * (1.f / DMODEL);
    const float var  = rq[0] * (1.f / DMODEL) - mu * mu;
    const float rinv = rsqrtf(var + 1e-5f);

    float4 g = ((const float4*)gamma)[tid];
    float4 be = ((const float4*)beta)[tid];
    float4 out;
    out.x = (s0 - mu) * rinv * g.x + be.x;
    out.y = (s1 - mu) * rinv * g.y + be.y;
    out.z = (s2 - mu) * rinv * g.z + be.z;
    out.w = (s3 - mu) * rinv * g.w + be.w;
    ((float4*)(y + (size_t)row * DMODEL))[tid] = out;
}

// ---------------------------------------------------------------------------
// launch
// ---------------------------------------------------------------------------
extern "C" void kernel_launch(void* const* d_in, const int* in_sizes, int n_in,
                              void* d_out, int out_size)
{
    const float* x  = (const float*)d_in[0];
    const float* Wq = (const float*)d_in[1];
    const float* Wk = (const float*)d_in[2];
    const float* Wv = (const float*)d_in[3];
    const float* Wo = (const float*)d_in[4];
    const float* W1 = (const float*)d_in[5];
    const float* W2 = (const float*)d_in[6];
    const float* g1 = (const float*)d_in[7];
    const float* b1 = (const float*)d_in[8];
    const float* g2 = (const float*)d_in[9];
    const float* b2 = (const float*)d_in[10];
    float* out = (float*)d_out;

    float *q, *k, *v, *attn, *proj, *x1, *ff;
    cudaGetSymbolAddress((void**)&q,    g_q);
    cudaGetSymbolAddress((void**)&k,    g_k);
    cudaGetSymbolAddress((void**)&v,    g_v);
    cudaGetSymbolAddress((void**)&attn, g_attn);
    cudaGetSymbolAddress((void**)&proj, g_proj);
    cudaGetSymbolAddress((void**)&x1,   g_x1);
    cudaGetSymbolAddress((void**)&ff,   g_ff);

    cudaFuncSetAttribute(gemm_mma<0>, cudaFuncAttributeMaxDynamicSharedMemorySize, GEMM_SMEM);
    cudaFuncSetAttribute(gemm_mma<1>, cudaFuncAttributeMaxDynamicSharedMemorySize, GEMM_SMEM);

    dim3 blk(256);

    // QKV projections
    dim3 gqkv(DMODEL / 128, TOKENS / 128);
    gemm_mma<0><<<gqkv, blk, GEMM_SMEM>>>(x, Wq, q, TOKENS, DMODEL, DMODEL);
    gemm_mma<0><<<gqkv, blk, GEMM_SMEM>>>(x, Wk, k, TOKENS, DMODEL, DMODEL);
    gemm_mma<0><<<gqkv, blk, GEMM_SMEM>>>(x, Wv, v, TOKENS, DMODEL, DMODEL);

    // attention
    dim3 gattn(SEQ / 64, 2 * NHEADS);
    flash_attn<<<gattn, dim3(128)>>>(q, k, v, attn);

    // output projection + residual + LN1
    gemm_mma<0><<<gqkv, blk, GEMM_SMEM>>>(attn, Wo, proj, TOKENS, DMODEL, DMODEL);
    add_ln<<<TOKENS, 256>>>(x, proj, g1, b1, x1);

    // FF1 (+GELU), FF2, residual + LN2
    dim3 gff1(DFF / 128, TOKENS / 128);
    gemm_mma<1><<<gff1, blk, GEMM_SMEM>>>(x1, W1, ff, TOKENS, DFF, DMODEL);
    gemm_mma<0><<<gqkv, blk, GEMM_SMEM>>>(ff, W2, proj, TOKENS, DMODEL, DFF);
    add_ln<<<TOKENS, 256>>>(x1, proj, g2, b2, out);
}

// round 4
// speedup vs baseline: 3.2863x; 1.8350x over previous
#include <cuda_runtime.h>
#include <math.h>
#include <cstdint>

// ---------------------------------------------------------------------------
// Problem constants
// ---------------------------------------------------------------------------
#define TOKENS 4096        // B*S = 2*2048
#define DMODEL 1024
#define DFF    4096
#define NHEADS 16
#define DK     64
#define SEQ    2048

// ---------------------------------------------------------------------------
// Scratch (device globals: no allocation allowed in kernel_launch)
// ---------------------------------------------------------------------------
__device__ float g_q   [TOKENS * DMODEL];
__device__ float g_k   [TOKENS * DMODEL];
__device__ float g_v   [TOKENS * DMODEL];
__device__ float g_attn[TOKENS * DMODEL];
__device__ float g_proj[TOKENS * DMODEL];
__device__ float g_x1  [TOKENS * DMODEL];
__device__ float g_ff  [TOKENS * DFF];

// ---------------------------------------------------------------------------
// Helpers
// ---------------------------------------------------------------------------
__device__ __forceinline__ uint32_t smem_u32(const void* p) {
    uint32_t a;
    asm("{ .reg .u64 t; cvta.to.shared.u64 t, %1; cvt.u32.u64 %0, t; }"
        : "=r"(a) : "l"(p));
    return a;
}

#define CP_ASYNC16(dst_u32, src_ptr) \
    asm volatile("cp.async.cg.shared.global [%0], [%1], 16;" \
        :: "r"(dst_u32), "l"(src_ptr))
#define CP_COMMIT() asm volatile("cp.async.commit_group;")
#define CP_WAIT(n)  asm volatile("cp.async.wait_group %0;" :: "n"(n))

// m16n8k8 tf32 HMMA, fp32 accumulate. a: 4 regs, b: 2 regs, c: 4 floats.
#define MMA_TF32(c, a, b) \
    asm volatile("mma.sync.aligned.m16n8k8.row.col.f32.tf32.tf32.f32 " \
        "{%0,%1,%2,%3}, {%4,%5,%6,%7}, {%8,%9}, {%0,%1,%2,%3};" \
        : "+f"((c)[0]), "+f"((c)[1]), "+f"((c)[2]), "+f"((c)[3]) \
        : "r"((a)[0]), "r"((a)[1]), "r"((a)[2]), "r"((a)[3]), \
          "r"((b)[0]), "r"((b)[1]))

// ---------------------------------------------------------------------------
// tf32 mma.sync GEMM:  C[M,N] = A[M,K] @ B[N,K]^T   (nn.Linear layout)
// Tile 128x128, BK=32, 256 threads (8 warps: 2 m x 4 n, 64x32 each),
// cp.async double-buffered SMEM. EPI: 0 = none, 1 = exact GELU.
// ---------------------------------------------------------------------------
#define LDPAD    36
#define TILE_F   (128 * LDPAD)
#define GEMM_SMEM (4 * TILE_F * 4)

template <int EPI>
__global__ __launch_bounds__(256)
void gemm_mma(const float* __restrict__ A, const float* __restrict__ B,
              float* __restrict__ C, int M, int N, int K)
{
    extern __shared__ float smem[];
    float* sA[2] = { smem,            smem + TILE_F };
    float* sB[2] = { smem + 2*TILE_F, smem + 3*TILE_F };
    const uint32_t sA_u[2] = { smem_u32(sA[0]), smem_u32(sA[1]) };
    const uint32_t sB_u[2] = { smem_u32(sB[0]), smem_u32(sB[1]) };

    const int tid = threadIdx.x;
    const int wid = tid >> 5;
    const int lid = tid & 31;
    const int gid = lid >> 2;
    const int tig = lid & 3;
    const int wm0 = (wid & 1) * 64;
    const int wn0 = (wid >> 1) * 32;
    const int bm  = blockIdx.y * 128;
    const int bn  = blockIdx.x * 128;

    const int ldRow = tid >> 3;
    const int ldC4  = (tid & 7) << 2;

    const float* Ab = A + (size_t)bm * K;
    const float* Bb = B + (size_t)bn * K;

    float acc[4][4][4];
#pragma unroll
    for (int i = 0; i < 4; i++)
#pragma unroll
        for (int j = 0; j < 4; j++)
#pragma unroll
            for (int r = 0; r < 4; r++) acc[i][j][r] = 0.f;

    const int KT = K >> 5;

    auto load_tile = [&](int kt, int buf) {
        const float* Ak = Ab + (size_t)kt * 32;
        const float* Bk = Bb + (size_t)kt * 32;
#pragma unroll
        for (int it = 0; it < 4; it++) {
            int row = ldRow + it * 32;
            uint32_t so = (uint32_t)(row * LDPAD + ldC4) * 4u;
            CP_ASYNC16(sA_u[buf] + so, Ak + (size_t)row * K + ldC4);
            CP_ASYNC16(sB_u[buf] + so, Bk + (size_t)row * K + ldC4);
        }
        CP_COMMIT();
    };

    load_tile(0, 0);

    for (int kt = 0; kt < KT; kt++) {
        const int buf = kt & 1;
        if (kt + 1 < KT) {
            load_tile(kt + 1, buf ^ 1);
            CP_WAIT(1);
        } else {
            CP_WAIT(0);
        }
        __syncthreads();

        const float* cA = sA[buf];
        const float* cB = sB[buf];
#pragma unroll
        for (int ks = 0; ks < 4; ks++) {
            const int k0 = ks * 8;
            uint32_t a[4][4], b[4][2];
#pragma unroll
            for (int fm = 0; fm < 4; fm++) {
                const float* p = cA + (wm0 + fm * 16 + gid) * LDPAD + k0 + tig;
                a[fm][0] = __float_as_uint(p[0]);
                a[fm][1] = __float_as_uint(p[8 * LDPAD]);
                a[fm][2] = __float_as_uint(p[4]);
                a[fm][3] = __float_as_uint(p[8 * LDPAD + 4]);
            }
#pragma unroll
            for (int fn = 0; fn < 4; fn++) {
                const float* p = cB + (wn0 + fn * 8 + gid) * LDPAD + k0 + tig;
                b[fn][0] = __float_as_uint(p[0]);
                b[fn][1] = __float_as_uint(p[4]);
            }
#pragma unroll
            for (int fm = 0; fm < 4; fm++)
#pragma unroll
                for (int fn = 0; fn < 4; fn++)
                    MMA_TF32(acc[fm][fn], a[fm], b[fn]);
        }
        __syncthreads();
    }

#pragma unroll
    for (int fm = 0; fm < 4; fm++) {
#pragma unroll
        for (int fn = 0; fn < 4; fn++) {
            float v[4];
#pragma unroll
            for (int r = 0; r < 4; r++) {
                float t = acc[fm][fn][r];
                if (EPI == 1) t = 0.5f * t * (1.f + erff(t * 0.70710678118654752f));
                v[r] = t;
            }
            const int row0 = bm + wm0 + fm * 16 + gid;
            const int col  = bn + wn0 + fn * 8 + tig * 2;
            *(float2*)(C + (size_t)row0 * N + col)       = make_float2(v[0], v[1]);
            *(float2*)(C + (size_t)(row0 + 8) * N + col) = make_float2(v[2], v[3]);
        }
    }
}

// ---------------------------------------------------------------------------
// Flash attention with tf32 mma.sync.
// CTA = 128 queries of one (b,h); 8 warps, each warp owns 16 query rows.
// Key tiles of 64, cp.async double-buffered K/V.
// S-fragments: warp computes S[16,64] (8 n-frags), online softmax on the
// fragments, then P re-laid into A-fragment format via intra-quad shuffles,
// O[16,64] += P @ V.
// ---------------------------------------------------------------------------
#define QPAD 68                       // Q/K row stride (floats): conflict-free frags
#define VPAD 72                       // V row stride: conflict-free col-major frags
#define FLASH_SMEM ((128*QPAD + 2*64*QPAD + 2*64*VPAD) * 4)   // 106496 B

__global__ __launch_bounds__(256)
void flash_mma(const float* __restrict__ Q, const float* __restrict__ K,
               const float* __restrict__ V, float* __restrict__ O)
{
    extern __shared__ float fs[];
    float* Qs = fs;                         // [128][QPAD]
    float* Ks[2] = { Qs + 128*QPAD, Qs + 128*QPAD + 64*QPAD };
    float* Vs[2] = { Ks[1] + 64*QPAD, Ks[1] + 64*QPAD + 64*VPAD };
    const uint32_t ks_u[2] = { smem_u32(Ks[0]), smem_u32(Ks[1]) };
    const uint32_t vs_u[2] = { smem_u32(Vs[0]), smem_u32(Vs[1]) };

    const int tid = threadIdx.x;
    const int wid = tid >> 5;
    const int lid = tid & 31;
    const int gid = lid >> 2;          // 0..7
    const int tig = lid & 3;           // 0..3
    const int q0  = blockIdx.x * 128;
    const int bh  = blockIdx.y;        // b*16 + h
    const int b   = bh >> 4;
    const int h   = bh & 15;
    const int m0  = wid * 16;          // warp's query stripe in tile

    const size_t base = (size_t)b * SEQ * DMODEL + h * DK;
    const float* Qb = Q + base;
    const float* Kb = K + base;
    const float* Vb = V + base;
    float*       Ob = O + base;

    // ---- load Q tile (scaled), rows 128 x 64 cols ----
    for (int s = tid; s < 128 * 16; s += 256) {
        int row = s >> 4;
        int c4  = (s & 15) << 2;
        float4 v = *(const float4*)(Qb + (size_t)(q0 + row) * DMODEL + c4);
        float* dst = Qs + row * QPAD + c4;
        dst[0] = v.x * 0.125f; dst[1] = v.y * 0.125f;
        dst[2] = v.z * 0.125f; dst[3] = v.w * 0.125f;
    }

    // ---- K/V tile loader (cp.async) ----
    auto load_kv = [&](int kt, int buf) {
        const float* Kt = Kb + (size_t)kt * 64 * DMODEL;
        const float* Vt = Vb + (size_t)kt * 64 * DMODEL;
#pragma unroll
        for (int it = 0; it < 4; it++) {
            int s   = tid + it * 256;          // 0..1023
            int row = s >> 4;
            int c4  = (s & 15) << 2;
            CP_ASYNC16(ks_u[buf] + (uint32_t)(row * QPAD + c4) * 4u,
                       Kt + (size_t)row * DMODEL + c4);
            CP_ASYNC16(vs_u[buf] + (uint32_t)(row * VPAD + c4) * 4u,
                       Vt + (size_t)row * DMODEL + c4);
        }
        CP_COMMIT();
    };

    load_kv(0, 0);

    float m[2] = { -1e30f, -1e30f };
    float l[2] = { 0.f, 0.f };
    float o[8][4];
#pragma unroll
    for (int d = 0; d < 8; d++)
#pragma unroll
        for (int r = 0; r < 4; r++) o[d][r] = 0.f;

    const int NT = SEQ / 64;

    for (int kt = 0; kt < NT; kt++) {
        const int buf = kt & 1;
        if (kt + 1 < NT) { load_kv(kt + 1, buf ^ 1); CP_WAIT(1); }
        else             { CP_WAIT(0); }
        __syncthreads();

        const float* Kc = Ks[buf];
        const float* Vc = Vs[buf];

        // ---- S = Q @ K^T : warp does [16, 64] ----
        float s[8][4];
#pragma unroll
        for (int nf = 0; nf < 8; nf++)
#pragma unroll
            for (int r = 0; r < 4; r++) s[nf][r] = 0.f;

#pragma unroll
        for (int kf = 0; kf < 8; kf++) {
            uint32_t a[4];
            const float* p = Qs + (m0 + gid) * QPAD + kf * 8 + tig;
            a[0] = __float_as_uint(p[0]);
            a[1] = __float_as_uint(p[8 * QPAD]);
            a[2] = __float_as_uint(p[4]);
            a[3] = __float_as_uint(p[8 * QPAD + 4]);
#pragma unroll
            for (int nf = 0; nf < 8; nf++) {
                const float* pb = Kc + (nf * 8 + gid) * QPAD + kf * 8 + tig;
                uint32_t bfr[2] = { __float_as_uint(pb[0]), __float_as_uint(pb[4]) };
                MMA_TF32(s[nf], a, bfr);
            }
        }

        // ---- online softmax on fragments ----
        // row0 = m0+gid (regs 0,1), row1 = row0+8 (regs 2,3); cols across quad
        float mx0 = -1e30f, mx1 = -1e30f;
#pragma unroll
        for (int nf = 0; nf < 8; nf++) {
            mx0 = fmaxf(mx0, fmaxf(s[nf][0], s[nf][1]));
            mx1 = fmaxf(mx1, fmaxf(s[nf][2], s[nf][3]));
        }
        mx0 = fmaxf(mx0, __shfl_xor_sync(0xffffffffu, mx0, 1));
        mx0 = fmaxf(mx0, __shfl_xor_sync(0xffffffffu, mx0, 2));
        mx1 = fmaxf(mx1, __shfl_xor_sync(0xffffffffu, mx1, 1));
        mx1 = fmaxf(mx1, __shfl_xor_sync(0xffffffffu, mx1, 2));

        const float mn0 = fmaxf(m[0], mx0);
        const float mn1 = fmaxf(m[1], mx1);
        const float al0 = __expf(m[0] - mn0);
        const float al1 = __expf(m[1] - mn1);

        float sum0 = 0.f, sum1 = 0.f;
#pragma unroll
        for (int nf = 0; nf < 8; nf++) {
            s[nf][0] = __expf(s[nf][0] - mn0);
            s[nf][1] = __expf(s[nf][1] - mn0);
            s[nf][2] = __expf(s[nf][2] - mn1);
            s[nf][3] = __expf(s[nf][3] - mn1);
            sum0 += s[nf][0] + s[nf][1];
            sum1 += s[nf][2] + s[nf][3];
        }
        sum0 += __shfl_xor_sync(0xffffffffu, sum0, 1);
        sum0 += __shfl_xor_sync(0xffffffffu, sum0, 2);
        sum1 += __shfl_xor_sync(0xffffffffu, sum1, 1);
        sum1 += __shfl_xor_sync(0xffffffffu, sum1, 2);

        l[0] = l[0] * al0 + sum0;
        l[1] = l[1] * al1 + sum1;
        m[0] = mn0;
        m[1] = mn1;

#pragma unroll
        for (int d = 0; d < 8; d++) {
            o[d][0] *= al0; o[d][1] *= al0;
            o[d][2] *= al1; o[d][3] *= al1;
        }

        // ---- O += P @ V ----
        // C-frag cols {2t,2t+1} -> A-frag cols {t, t+4} via intra-quad shfl
        const int lbase = lid & ~3;
        const int src0  = lbase | (tig >> 1);
        const int src1  = src0 + 2;
        const bool oddc = (tig & 1);
#pragma unroll
        for (int j = 0; j < 8; j++) {
            float v00 = __shfl_sync(0xffffffffu, s[j][0], src0);
            float v01 = __shfl_sync(0xffffffffu, s[j][1], src0);
            float v20 = __shfl_sync(0xffffffffu, s[j][2], src0);
            float v21 = __shfl_sync(0xffffffffu, s[j][3], src0);
            float w00 = __shfl_sync(0xffffffffu, s[j][0], src1);
            float w01 = __shfl_sync(0xffffffffu, s[j][1], src1);
            float w20 = __shfl_sync(0xffffffffu, s[j][2], src1);
            float w21 = __shfl_sync(0xffffffffu, s[j][3], src1);
            uint32_t a[4];
            a[0] = __float_as_uint(oddc ? v01 : v00);
            a[1] = __float_as_uint(oddc ? v21 : v20);
            a[2] = __float_as_uint(oddc ? w01 : w00);
            a[3] = __float_as_uint(oddc ? w21 : w20);
#pragma unroll
            for (int d = 0; d < 8; d++) {
                const float* pv = Vc + (j * 8 + tig) * VPAD + d * 8 + gid;
                uint32_t bfr[2] = { __float_as_uint(pv[0]),
                                    __float_as_uint(pv[4 * VPAD]) };
                MMA_TF32(o[d], a, bfr);
            }
        }
        __syncthreads();
    }

    // ---- epilogue: O / l ----
    const float inv0 = 1.f / l[0];
    const float inv1 = 1.f / l[1];
    const int row0 = q0 + m0 + gid;
#pragma unroll
    for (int d = 0; d < 8; d++) {
        const int col = d * 8 + tig * 2;
        *(float2*)(Ob + (size_t)row0 * DMODEL + col) =
            make_float2(o[d][0] * inv0, o[d][1] * inv0);
        *(float2*)(Ob + (size_t)(row0 + 8) * DMODEL + col) =
            make_float2(o[d][2] * inv1, o[d][3] * inv1);
    }
}

// ---------------------------------------------------------------------------
// y = LayerNorm(a + b) * gamma + beta
// ---------------------------------------------------------------------------
__global__ __launch_bounds__(256)
void add_ln(const float* __restrict__ a, const float* __restrict__ b,
            const float* __restrict__ gamma, const float* __restrict__ beta,
            float* __restrict__ y)
{
    const int row = blockIdx.x;
    const int tid = threadIdx.x;
    __shared__ float rs[256], rq[256];

    float4 va = ((const float4*)(a + (size_t)row * DMODEL))[tid];
    float4 vb = ((const float4*)(b + (size_t)row * DMODEL))[tid];
    float s0 = va.x + vb.x, s1 = va.y + vb.y, s2 = va.z + vb.z, s3 = va.w + vb.w;

    rs[tid] = s0 + s1 + s2 + s3;
    rq[tid] = s0 * s0 + s1 * s1 + s2 * s2 + s3 * s3;
    __syncthreads();
#pragma unroll
    for (int off = 128; off > 0; off >>= 1) {
        if (tid < off) { rs[tid] += rs[tid + off]; rq[tid] += rq[tid + off]; }
        __syncthreads();
    }
    const float mu   = rs[0] * (1.f / DMODEL);
    const float var  = rq[0] * (1.f / DMODEL) - mu * mu;
    const float rinv = rsqrtf(var + 1e-5f);

    float4 g = ((const float4*)gamma)[tid];
    float4 be = ((const float4*)beta)[tid];
    float4 out;
    out.x = (s0 - mu) * rinv * g.x + be.x;
    out.y = (s1 - mu) * rinv * g.y + be.y;
    out.z = (s2 - mu) * rinv * g.z + be.z;
    out.w = (s3 - mu) * rinv * g.w + be.w;
    ((float4*)(y + (size_t)row * DMODEL))[tid] = out;
}

// ---------------------------------------------------------------------------
// launch
// ---------------------------------------------------------------------------
extern "C" void kernel_launch(void* const* d_in, const int* in_sizes, int n_in,
                              void* d_out, int out_size)
{
    const float* x  = (const float*)d_in[0];
    const float* Wq = (const float*)d_in[1];
    const float* Wk = (const float*)d_in[2];
    const float* Wv = (const float*)d_in[3];
    const float* Wo = (const float*)d_in[4];
    const float* W1 = (const float*)d_in[5];
    const float* W2 = (const float*)d_in[6];
    const float* g1 = (const float*)d_in[7];
    const float* b1 = (const float*)d_in[8];
    const float* g2 = (const float*)d_in[9];
    const float* b2 = (const float*)d_in[10];
    float* out = (float*)d_out;

    float *q, *k, *v, *attn, *proj, *x1, *ff;
    cudaGetSymbolAddress((void**)&q,    g_q);
    cudaGetSymbolAddress((void**)&k,    g_k);
    cudaGetSymbolAddress((void**)&v,    g_v);
    cudaGetSymbolAddress((void**)&attn, g_attn);
    cudaGetSymbolAddress((void**)&proj, g_proj);
    cudaGetSymbolAddress((void**)&x1,   g_x1);
    cudaGetSymbolAddress((void**)&ff,   g_ff);

    cudaFuncSetAttribute(gemm_mma<0>, cudaFuncAttributeMaxDynamicSharedMemorySize, GEMM_SMEM);
    cudaFuncSetAttribute(gemm_mma<1>, cudaFuncAttributeMaxDynamicSharedMemorySize, GEMM_SMEM);
    cudaFuncSetAttribute(flash_mma,   cudaFuncAttributeMaxDynamicSharedMemorySize, FLASH_SMEM);

    dim3 blk(256);

    // QKV projections
    dim3 gqkv(DMODEL / 128, TOKENS / 128);
    gemm_mma<0><<<gqkv, blk, GEMM_SMEM>>>(x, Wq, q, TOKENS, DMODEL, DMODEL);
    gemm_mma<0><<<gqkv, blk, GEMM_SMEM>>>(x, Wk, k, TOKENS, DMODEL, DMODEL);
    gemm_mma<0><<<gqkv, blk, GEMM_SMEM>>>(x, Wv, v, TOKENS, DMODEL, DMODEL);

    // attention (tensor-core flash)
    dim3 gattn(SEQ / 128, 2 * NHEADS);
    flash_mma<<<gattn, blk, FLASH_SMEM>>>(q, k, v, attn);

    // output projection + residual + LN1
    gemm_mma<0><<<gqkv, blk, GEMM_SMEM>>>(attn, Wo, proj, TOKENS, DMODEL, DMODEL);
    add_ln<<<TOKENS, 256>>>(x, proj, g1, b1, x1);

    // FF1 (+GELU), FF2, residual + LN2
    dim3 gff1(DFF / 128, TOKENS / 128);
    gemm_mma<1><<<gff1, blk, GEMM_SMEM>>>(x1, W1, ff, TOKENS, DFF, DMODEL);
    gemm_mma<0><<<gqkv, blk, GEMM_SMEM>>>(ff, W2, proj, TOKENS, DMODEL, DFF);
    add_ln<<<TOKENS, 256>>>(x1, proj, g2, b2, out);
}

// round 5
// speedup vs baseline: 5.8021x; 1.7655x over previous
#include <cuda_runtime.h>
#include <cuda_fp16.h>
#include <math.h>
#include <cstdint>

// ---------------------------------------------------------------------------
// Problem constants
// ---------------------------------------------------------------------------
#define TOKENS 4096        // B*S = 2*2048
#define DMODEL 1024
#define DFF    4096
#define NHEADS 16
#define DK     64
#define SEQ    2048

// ---------------------------------------------------------------------------
// Scratch (device globals)
// ---------------------------------------------------------------------------
__device__ __half hx   [TOKENS * DMODEL];
__device__ __half hWq  [DMODEL * DMODEL];
__device__ __half hWk  [DMODEL * DMODEL];
__device__ __half hWv  [DMODEL * DMODEL];
__device__ __half hWo  [DMODEL * DMODEL];
__device__ __half hW1  [DFF * DMODEL];
__device__ __half hW2  [DMODEL * DFF];
__device__ __half hq   [TOKENS * DMODEL];   // pre-scaled by 1/8
__device__ __half hk   [TOKENS * DMODEL];
__device__ __half hvt  [TOKENS * DMODEL];   // V transposed: [b][h][d][s]
__device__ __half hattn[TOKENS * DMODEL];
__device__ __half hx1  [TOKENS * DMODEL];
__device__ __half hff  [TOKENS * DFF];
__device__ float  g_proj[TOKENS * DMODEL];
__device__ float  g_x1 [TOKENS * DMODEL];

// ---------------------------------------------------------------------------
// Helpers
// ---------------------------------------------------------------------------
__device__ __forceinline__ uint32_t smem_u32(const void* p) {
    uint32_t a;
    asm("{ .reg .u64 t; cvta.to.shared.u64 t, %1; cvt.u32.u64 %0, t; }"
        : "=r"(a) : "l"(p));
    return a;
}

#define CP_ASYNC16(dst_u32, src_ptr) \
    asm volatile("cp.async.cg.shared.global [%0], [%1], 16;" \
        :: "r"(dst_u32), "l"(src_ptr))
#define CP_COMMIT() asm volatile("cp.async.commit_group;")
#define CP_WAIT(n)  asm volatile("cp.async.wait_group %0;" :: "n"(n))

// m16n8k16 fp16 HMMA, fp32 accumulate. a: 4 b32 regs, b: 2 b32 regs, c: 4 f32.
#define MMA_F16(c, a, b) \
    asm volatile("mma.sync.aligned.m16n8k16.row.col.f32.f16.f16.f32 " \
        "{%0,%1,%2,%3}, {%4,%5,%6,%7}, {%8,%9}, {%0,%1,%2,%3};" \
        : "+f"((c)[0]), "+f"((c)[1]), "+f"((c)[2]), "+f"((c)[3]) \
        : "r"((a)[0]), "r"((a)[1]), "r"((a)[2]), "r"((a)[3]), \
          "r"((b)[0]), "r"((b)[1]))

__device__ __forceinline__ uint32_t lds32h(const __half* p) {
    return *reinterpret_cast<const uint32_t*>(p);
}
__device__ __forceinline__ uint32_t pack_h2(float lo, float hi) {
    __half2 h = __floats2half2_rn(lo, hi);
    return *reinterpret_cast<uint32_t*>(&h);
}

// ---------------------------------------------------------------------------
// fp32 -> fp16 conversion (n multiple of 4)
// ---------------------------------------------------------------------------
__global__ __launch_bounds__(256)
void f2h(const float* __restrict__ in, __half* __restrict__ out, int n)
{
    int i = (blockIdx.x * 256 + threadIdx.x) * 4;
    if (i < n) {
        float4 v = *(const float4*)(in + i);
        *(__half2*)(out + i)     = __floats2half2_rn(v.x, v.y);
        *(__half2*)(out + i + 2) = __floats2half2_rn(v.z, v.w);
    }
}

// ---------------------------------------------------------------------------
// fp16 mma.sync GEMM:  C[M,N] = A[M,K] @ B[N,K]^T   (both fp16 K-major)
// Tile 128x128, BK=64 halves (128B rows), 256 threads (8 warps 2m x 4n,
// 64x32 each), cp.async double-buffered.
// EPI: 0 = fp16 out, 1 = fp16 out * 0.125 (Q), 2 = fp16 V transposed store,
//      3 = exact GELU -> fp16, 4 = fp32 out.
// ---------------------------------------------------------------------------
#define HSTR  72                     // halves per smem row (64 + 8 pad)
#define HTILE (128 * HSTR)           // halves per operand buffer
#define GEMMH_SMEM (4 * HTILE * 2)   // 73728 B

template <int EPI>
__global__ __launch_bounds__(256)
void gemm_h(const __half* __restrict__ A, const __half* __restrict__ B,
            void* __restrict__ Cv, int M, int N, int K)
{
    extern __shared__ __half hsm[];
    __half* sA[2] = { hsm,             hsm + HTILE };
    __half* sB[2] = { hsm + 2 * HTILE, hsm + 3 * HTILE };
    const uint32_t sA_u[2] = { smem_u32(sA[0]), smem_u32(sA[1]) };
    const uint32_t sB_u[2] = { smem_u32(sB[0]), smem_u32(sB[1]) };

    const int tid = threadIdx.x;
    const int wid = tid >> 5;
    const int lid = tid & 31;
    const int gid = lid >> 2;          // 0..7
    const int tig = lid & 3;           // 0..3
    const int wm0 = (wid & 1) * 64;
    const int wn0 = (wid >> 1) * 32;
    const int bm  = blockIdx.y * 128;
    const int bn  = blockIdx.x * 128;

    const int ldRow = tid >> 3;        // 0..31
    const int ldC8  = (tid & 7) << 3;  // half offset 0,8,...,56

    const __half* Ab = A + (size_t)bm * K;
    const __half* Bb = B + (size_t)bn * K;

    float acc[4][4][4];
#pragma unroll
    for (int i = 0; i < 4; i++)
#pragma unroll
        for (int j = 0; j < 4; j++)
#pragma unroll
            for (int r = 0; r < 4; r++) acc[i][j][r] = 0.f;

    const int KT = K >> 6;             // BK = 64 halves

    auto load_tile = [&](int kt, int buf) {
        const __half* Ak = Ab + (size_t)kt * 64;
        const __half* Bk = Bb + (size_t)kt * 64;
#pragma unroll
        for (int it = 0; it < 4; it++) {
            int row = ldRow + it * 32;
            uint32_t so = (uint32_t)(row * HSTR + ldC8) * 2u;
            CP_ASYNC16(sA_u[buf] + so, Ak + (size_t)row * K + ldC8);
            CP_ASYNC16(sB_u[buf] + so, Bk + (size_t)row * K + ldC8);
        }
        CP_COMMIT();
    };

    load_tile(0, 0);

    for (int kt = 0; kt < KT; kt++) {
        const int buf = kt & 1;
        if (kt + 1 < KT) { load_tile(kt + 1, buf ^ 1); CP_WAIT(1); }
        else             { CP_WAIT(0); }
        __syncthreads();

        const __half* cA = sA[buf];
        const __half* cB = sB[buf];
#pragma unroll
        for (int ks = 0; ks < 4; ks++) {
            const int k0 = ks * 16;
            uint32_t a[4][4], b[4][2];
#pragma unroll
            for (int fm = 0; fm < 4; fm++) {
                const __half* p = cA + (wm0 + fm * 16 + gid) * HSTR + k0 + 2 * tig;
                a[fm][0] = lds32h(p);
                a[fm][1] = lds32h(p + 8 * HSTR);
                a[fm][2] = lds32h(p + 8);
                a[fm][3] = lds32h(p + 8 * HSTR + 8);
            }
#pragma unroll
            for (int fn = 0; fn < 4; fn++) {
                const __half* p = cB + (wn0 + fn * 8 + gid) * HSTR + k0 + 2 * tig;
                b[fn][0] = lds32h(p);
                b[fn][1] = lds32h(p + 8);
            }
#pragma unroll
            for (int fm = 0; fm < 4; fm++)
#pragma unroll
                for (int fn = 0; fn < 4; fn++)
                    MMA_F16(acc[fm][fn], a[fm], b[fn]);
        }
        __syncthreads();
    }

    // --- epilogue ---
#pragma unroll
    for (int fm = 0; fm < 4; fm++) {
#pragma unroll
        for (int fn = 0; fn < 4; fn++) {
            float v[4];
#pragma unroll
            for (int r = 0; r < 4; r++) {
                float t = acc[fm][fn][r];
                if (EPI == 1) t *= 0.125f;
                if (EPI == 3) t = 0.5f * t * (1.f + erff(t * 0.70710678118654752f));
                v[r] = t;
            }
            const int row0 = bm + wm0 + fm * 16 + gid;
            const int col  = bn + wn0 + fn * 8 + tig * 2;
            if (EPI == 4) {
                float* C = (float*)Cv;
                *(float2*)(C + (size_t)row0 * N + col)       = make_float2(v[0], v[1]);
                *(float2*)(C + (size_t)(row0 + 8) * N + col) = make_float2(v[2], v[3]);
            } else if (EPI == 2) {
                // V transposed store: element (r,c) -> vt[((b*16+h)*64+d)*SEQ + s]
                __half* C = (__half*)Cv;
#pragma unroll
                for (int ri = 0; ri < 2; ri++) {
#pragma unroll
                    for (int ci = 0; ci < 2; ci++) {
                        int r = row0 + ri * 8;
                        int c = col + ci;
                        int bb = r >> 11, ss = r & 2047;
                        int hh = c >> 6,  dd = c & 63;
                        C[(((size_t)(bb * 16 + hh)) * 64 + dd) * SEQ + ss] =
                            __float2half(v[ri * 2 + ci]);
                    }
                }
            } else {
                __half* C = (__half*)Cv;
                *(__half2*)(C + (size_t)row0 * N + col) =
                    __floats2half2_rn(v[0], v[1]);
                *(__half2*)(C + (size_t)(row0 + 8) * N + col) =
                    __floats2half2_rn(v[2], v[3]);
            }
        }
    }
}

// ---------------------------------------------------------------------------
// Flash attention, fp16 mma.sync (m16n8k16).
// CTA = 128 queries of one (b,h); 8 warps each own 16 query rows.
// Q pre-scaled by 1/8. K tiles [key][d], V tiles transposed [d][key].
// S C-fragments pack directly into P A-fragments (no shuffles).
// ---------------------------------------------------------------------------
#define FQS 72
#define FLASHH_SMEM ((128 * FQS + 4 * 64 * FQS) * 2)   // 55296 B

__global__ __launch_bounds__(256)
void flash_h(const __half* __restrict__ Q, const __half* __restrict__ K,
             const __half* __restrict__ Vt, __half* __restrict__ Oa)
{
    extern __shared__ __half fsh[];
    __half* Qs = fsh;                                   // [128][FQS]
    __half* Ks[2] = { Qs + 128 * FQS, Qs + 128 * FQS + 64 * FQS };
    __half* Vs[2] = { Ks[1] + 64 * FQS, Ks[1] + 2 * 64 * FQS };
    const uint32_t ks_u[2] = { smem_u32(Ks[0]), smem_u32(Ks[1]) };
    const uint32_t vs_u[2] = { smem_u32(Vs[0]), smem_u32(Vs[1]) };
    const uint32_t qs_u = smem_u32(Qs);

    const int tid = threadIdx.x;
    const int wid = tid >> 5;
    const int lid = tid & 31;
    const int gid = lid >> 2;
    const int tig = lid & 3;
    const int q0  = blockIdx.x * 128;
    const int bh  = blockIdx.y;
    const int b   = bh >> 4;
    const int h   = bh & 15;
    const int m0  = wid * 16;

    const size_t base = (size_t)b * SEQ * DMODEL + h * DK;
    const __half* Qb = Q + base;
    const __half* Kb = K + base;
    const __half* Vb = Vt + ((size_t)(b * 16 + h)) * 64 * SEQ;
    __half*       Ob = Oa + base;

    // ---- Q tile: 128 rows x 64 halves (cp.async, own group) ----
#pragma unroll
    for (int it = 0; it < 4; it++) {
        int s   = tid + it * 256;
        int row = s >> 3;
        int c8  = (s & 7) << 3;
        CP_ASYNC16(qs_u + (uint32_t)(row * FQS + c8) * 2u,
                   Qb + (size_t)(q0 + row) * DMODEL + c8);
    }
    CP_COMMIT();

    // ---- K/V tile loader ----
    auto load_kv = [&](int kt, int buf) {
        const __half* Kt = Kb + (size_t)kt * 64 * DMODEL;
        const __half* Vtt = Vb + kt * 64;
#pragma unroll
        for (int it = 0; it < 2; it++) {
            int s   = tid + it * 256;         // 0..511
            int row = s >> 3;                 // 0..63
            int c8  = (s & 7) << 3;
            CP_ASYNC16(ks_u[buf] + (uint32_t)(row * FQS + c8) * 2u,
                       Kt + (size_t)row * DMODEL + c8);
            CP_ASYNC16(vs_u[buf] + (uint32_t)(row * FQS + c8) * 2u,
                       Vtt + (size_t)row * SEQ + c8);
        }
        CP_COMMIT();
    };

    load_kv(0, 0);

    float m[2] = { -1e30f, -1e30f };
    float l[2] = { 0.f, 0.f };
    float o[8][4];
#pragma unroll
    for (int d = 0; d < 8; d++)
#pragma unroll
        for (int r = 0; r < 4; r++) o[d][r] = 0.f;

    const int NT = SEQ / 64;

    for (int kt = 0; kt < NT; kt++) {
        const int buf = kt & 1;
        if (kt + 1 < NT) { load_kv(kt + 1, buf ^ 1); CP_WAIT(1); }
        else             { CP_WAIT(0); }
        __syncthreads();

        const __half* Kc = Ks[buf];
        const __half* Vc = Vs[buf];

        // ---- S = Q @ K^T : warp [16, 64] ----
        float s[8][4];
#pragma unroll
        for (int nf = 0; nf < 8; nf++)
#pragma unroll
            for (int r = 0; r < 4; r++) s[nf][r] = 0.f;

#pragma unroll
        for (int kf = 0; kf < 4; kf++) {
            uint32_t a[4];
            const __half* p = Qs + (m0 + gid) * FQS + kf * 16 + 2 * tig;
            a[0] = lds32h(p);
            a[1] = lds32h(p + 8 * FQS);
            a[2] = lds32h(p + 8);
            a[3] = lds32h(p + 8 * FQS + 8);
#pragma unroll
            for (int nf = 0; nf < 8; nf++) {
                const __half* pb = Kc + (nf * 8 + gid) * FQS + kf * 16 + 2 * tig;
                uint32_t bfr[2] = { lds32h(pb), lds32h(pb + 8) };
                MMA_F16(s[nf], a, bfr);
            }
        }

        // ---- online softmax (Q pre-scaled; S already scaled) ----
        float mx0 = -1e30f, mx1 = -1e30f;
#pragma unroll
        for (int nf = 0; nf < 8; nf++) {
            mx0 = fmaxf(mx0, fmaxf(s[nf][0], s[nf][1]));
            mx1 = fmaxf(mx1, fmaxf(s[nf][2], s[nf][3]));
        }
        mx0 = fmaxf(mx0, __shfl_xor_sync(0xffffffffu, mx0, 1));
        mx0 = fmaxf(mx0, __shfl_xor_sync(0xffffffffu, mx0, 2));
        mx1 = fmaxf(mx1, __shfl_xor_sync(0xffffffffu, mx1, 1));
        mx1 = fmaxf(mx1, __shfl_xor_sync(0xffffffffu, mx1, 2));

        const float mn0 = fmaxf(m[0], mx0);
        const float mn1 = fmaxf(m[1], mx1);
        const float al0 = __expf(m[0] - mn0);
        const float al1 = __expf(m[1] - mn1);

        float sum0 = 0.f, sum1 = 0.f;
#pragma unroll
        for (int nf = 0; nf < 8; nf++) {
            s[nf][0] = __expf(s[nf][0] - mn0);
            s[nf][1] = __expf(s[nf][1] - mn0);
            s[nf][2] = __expf(s[nf][2] - mn1);
            s[nf][3] = __expf(s[nf][3] - mn1);
            sum0 += s[nf][0] + s[nf][1];
            sum1 += s[nf][2] + s[nf][3];
        }
        sum0 += __shfl_xor_sync(0xffffffffu, sum0, 1);
        sum0 += __shfl_xor_sync(0xffffffffu, sum0, 2);
        sum1 += __shfl_xor_sync(0xffffffffu, sum1, 1);
        sum1 += __shfl_xor_sync(0xffffffffu, sum1, 2);

        l[0] = l[0] * al0 + sum0;
        l[1] = l[1] * al1 + sum1;
        m[0] = mn0;
        m[1] = mn1;

#pragma unroll
        for (int d = 0; d < 8; d++) {
            o[d][0] *= al0; o[d][1] *= al0;
            o[d][2] *= al1; o[d][3] *= al1;
        }

        // ---- O += P @ V : P packs directly into fp16 A-fragments ----
#pragma unroll
        for (int c = 0; c < 4; c++) {
            uint32_t a[4];
            a[0] = pack_h2(s[2*c][0],   s[2*c][1]);
            a[1] = pack_h2(s[2*c][2],   s[2*c][3]);
            a[2] = pack_h2(s[2*c+1][0], s[2*c+1][1]);
            a[3] = pack_h2(s[2*c+1][2], s[2*c+1][3]);
#pragma unroll
            for (int d = 0; d < 8; d++) {
                const __half* pv = Vc + (d * 8 + gid) * FQS + c * 16 + 2 * tig;
                uint32_t bfr[2] = { lds32h(pv), lds32h(pv + 8) };
                MMA_F16(o[d], a, bfr);
            }
        }
        __syncthreads();
    }

    // ---- epilogue: O / l -> fp16 ----
    const float inv0 = 1.f / l[0];
    const float inv1 = 1.f / l[1];
    const int row0 = q0 + m0 + gid;
#pragma unroll
    for (int d = 0; d < 8; d++) {
        const int col = d * 8 + tig * 2;
        *(__half2*)(Ob + (size_t)row0 * DMODEL + col) =
            __floats2half2_rn(o[d][0] * inv0, o[d][1] * inv0);
        *(__half2*)(Ob + (size_t)(row0 + 8) * DMODEL + col) =
            __floats2half2_rn(o[d][2] * inv1, o[d][3] * inv1);
    }
}

// ---------------------------------------------------------------------------
// y = LayerNorm(a + b) * gamma + beta; dual output (fp32 + fp16)
// ---------------------------------------------------------------------------
__global__ __launch_bounds__(256)
void add_ln2(const float* __restrict__ a, const float* __restrict__ b,
             const float* __restrict__ gamma, const float* __restrict__ beta,
             float* __restrict__ y, __half* __restrict__ yh)
{
    const int row = blockIdx.x;
    const int tid = threadIdx.x;
    __shared__ float rs[256], rq[256];

    float4 va = ((const float4*)(a + (size_t)row * DMODEL))[tid];
    float4 vb = ((const float4*)(b + (size_t)row * DMODEL))[tid];
    float s0 = va.x + vb.x, s1 = va.y + vb.y, s2 = va.z + vb.z, s3 = va.w + vb.w;

    rs[tid] = s0 + s1 + s2 + s3;
    rq[tid] = s0 * s0 + s1 * s1 + s2 * s2 + s3 * s3;
    __syncthreads();
#pragma unroll
    for (int off = 128; off > 0; off >>= 1) {
        if (tid < off) { rs[tid] += rs[tid + off]; rq[tid] += rq[tid + off]; }
        __syncthreads();
    }
    const float mu   = rs[0] * (1.f / DMODEL);
    const float var  = rq[0] * (1.f / DMODEL) - mu * mu;
    const float rinv = rsqrtf(var + 1e-5f);

    float4 g  = ((const float4*)gamma)[tid];
    float4 be = ((const float4*)beta)[tid];
    float4 out;
    out.x = (s0 - mu) * rinv * g.x + be.x;
    out.y = (s1 - mu) * rinv * g.y + be.y;
    out.z = (s2 - mu) * rinv * g.z + be.z;
    out.w = (s3 - mu) * rinv * g.w + be.w;
    ((float4*)(y + (size_t)row * DMODEL))[tid] = out;

    __half* hp = yh + (size_t)row * DMODEL + tid * 4;
    *(__half2*)(hp)     = __floats2half2_rn(out.x, out.y);
    *(__half2*)(hp + 2) = __floats2half2_rn(out.z, out.w);
}

// ---------------------------------------------------------------------------
// launch
// ---------------------------------------------------------------------------
extern "C" void kernel_launch(void* const* d_in, const int* in_sizes, int n_in,
                              void* d_out, int out_size)
{
    const float* x  = (const float*)d_in[0];
    const float* Wq = (const float*)d_in[1];
    const float* Wk = (const float*)d_in[2];
    const float* Wv = (const float*)d_in[3];
    const float* Wo = (const float*)d_in[4];
    const float* W1 = (const float*)d_in[5];
    const float* W2 = (const float*)d_in[6];
    const float* g1 = (const float*)d_in[7];
    const float* b1 = (const float*)d_in[8];
    const float* g2 = (const float*)d_in[9];
    const float* b2 = (const float*)d_in[10];
    float* out = (float*)d_out;

    __half *px, *pwq, *pwk, *pwv, *pwo, *pw1, *pw2;
    __half *pq, *pk, *pvt, *pattn, *px1h, *pff;
    float *pproj, *px1;
    cudaGetSymbolAddress((void**)&px,   hx);
    cudaGetSymbolAddress((void**)&pwq,  hWq);
    cudaGetSymbolAddress((void**)&pwk,  hWk);
    cudaGetSymbolAddress((void**)&pwv,  hWv);
    cudaGetSymbolAddress((void**)&pwo,  hWo);
    cudaGetSymbolAddress((void**)&pw1,  hW1);
    cudaGetSymbolAddress((void**)&pw2,  hW2);
    cudaGetSymbolAddress((void**)&pq,   hq);
    cudaGetSymbolAddress((void**)&pk,   hk);
    cudaGetSymbolAddress((void**)&pvt,  hvt);
    cudaGetSymbolAddress((void**)&pattn,hattn);
    cudaGetSymbolAddress((void**)&px1h, hx1);
    cudaGetSymbolAddress((void**)&pff,  hff);
    cudaGetSymbolAddress((void**)&pproj,g_proj);
    cudaGetSymbolAddress((void**)&px1,  g_x1);

    cudaFuncSetAttribute(gemm_h<0>, cudaFuncAttributeMaxDynamicSharedMemorySize, GEMMH_SMEM);
    cudaFuncSetAttribute(gemm_h<1>, cudaFuncAttributeMaxDynamicSharedMemorySize, GEMMH_SMEM);
    cudaFuncSetAttribute(gemm_h<2>, cudaFuncAttributeMaxDynamicSharedMemorySize, GEMMH_SMEM);
    cudaFuncSetAttribute(gemm_h<3>, cudaFuncAttributeMaxDynamicSharedMemorySize, GEMMH_SMEM);
    cudaFuncSetAttribute(gemm_h<4>, cudaFuncAttributeMaxDynamicSharedMemorySize, GEMMH_SMEM);
    cudaFuncSetAttribute(flash_h,   cudaFuncAttributeMaxDynamicSharedMemorySize, FLASHH_SMEM);

    // ---- fp32 -> fp16 conversions ----
    auto cv = [&](const float* src, __half* dst, int n) {
        f2h<<<n / 1024, 256>>>(src, dst, n);
    };
    cv(x,  px,  TOKENS * DMODEL);
    cv(Wq, pwq, DMODEL * DMODEL);
    cv(Wk, pwk, DMODEL * DMODEL);
    cv(Wv, pwv, DMODEL * DMODEL);
    cv(Wo, pwo, DMODEL * DMODEL);
    cv(W1, pw1, DFF * DMODEL);
    cv(W2, pw2, DMODEL * DFF);

    dim3 blk(256);
    dim3 gqkv(DMODEL / 128, TOKENS / 128);

    // QKV projections (Q pre-scaled, V stored transposed)
    gemm_h<1><<<gqkv, blk, GEMMH_SMEM>>>(px, pwq, pq,  TOKENS, DMODEL, DMODEL);
    gemm_h<0><<<gqkv, blk, GEMMH_SMEM>>>(px, pwk, pk,  TOKENS, DMODEL, DMODEL);
    gemm_h<2><<<gqkv, blk, GEMMH_SMEM>>>(px, pwv, pvt, TOKENS, DMODEL, DMODEL);

    // attention
    dim3 gattn(SEQ / 128, 2 * NHEADS);
    flash_h<<<gattn, blk, FLASHH_SMEM>>>(pq, pk, pvt, pattn);

    // output projection + residual + LN1
    gemm_h<4><<<gqkv, blk, GEMMH_SMEM>>>(pattn, pwo, pproj, TOKENS, DMODEL, DMODEL);
    add_ln2<<<TOKENS, 256>>>(x, pproj, g1, b1, px1, px1h);

    // FF1 (+GELU), FF2, residual + LN2
    dim3 gff1(DFF / 128, TOKENS / 128);
    gemm_h<3><<<gff1, blk, GEMMH_SMEM>>>(px1h, pw1, pff,  TOKENS, DFF, DMODEL);
    gemm_h<4><<<gqkv, blk, GEMMH_SMEM>>>(pff, pw2, pproj, TOKENS, DMODEL, DFF);
    add_ln2<<<TOKENS, 256>>>(px1, pproj, g2, b2, out, px1h);
}

// round 6
// speedup vs baseline: 6.7973x; 1.1715x over previous
#include <cuda_runtime.h>
#include <cuda_fp16.h>
#include <math.h>
#include <cstdint>

// ---------------------------------------------------------------------------
// Problem constants
// ---------------------------------------------------------------------------
#define TOKENS 4096        // B*S = 2*2048
#define DMODEL 1024
#define DFF    4096
#define NHEADS 16
#define DK     64
#define SEQ    2048

// ---------------------------------------------------------------------------
// Scratch (device globals)
// ---------------------------------------------------------------------------
__device__ __half hx   [TOKENS * DMODEL];
__device__ __half hWq  [DMODEL * DMODEL];
__device__ __half hWk  [DMODEL * DMODEL];
__device__ __half hWv  [DMODEL * DMODEL];
__device__ __half hWo  [DMODEL * DMODEL];
__device__ __half hW1  [DFF * DMODEL];
__device__ __half hW2  [DMODEL * DFF];
__device__ __half hq   [TOKENS * DMODEL];   // pre-scaled by 1/8
__device__ __half hk   [TOKENS * DMODEL];
__device__ __half hvt  [TOKENS * DMODEL];   // V transposed: [b][h][d][s]
__device__ __half hattn[TOKENS * DMODEL];
__device__ __half hx1  [TOKENS * DMODEL];
__device__ __half hff  [TOKENS * DFF];
__device__ float  g_proj[TOKENS * DMODEL];
__device__ float  g_x1 [TOKENS * DMODEL];

// ---------------------------------------------------------------------------
// Helpers
// ---------------------------------------------------------------------------
__device__ __forceinline__ uint32_t smem_u32(const void* p) {
    uint32_t a;
    asm("{ .reg .u64 t; cvta.to.shared.u64 t, %1; cvt.u32.u64 %0, t; }"
        : "=r"(a) : "l"(p));
    return a;
}

#define CP_ASYNC16(dst_u32, src_ptr) \
    asm volatile("cp.async.cg.shared.global [%0], [%1], 16;" \
        :: "r"(dst_u32), "l"(src_ptr))
#define CP_COMMIT() asm volatile("cp.async.commit_group;")
#define CP_WAIT(n)  asm volatile("cp.async.wait_group %0;" :: "n"(n))

// m16n8k16 fp16 HMMA, fp32 accumulate.
#define MMA_F16(c, a0, a1, a2, a3, b0, b1) \
    asm volatile("mma.sync.aligned.m16n8k16.row.col.f32.f16.f16.f32 " \
        "{%0,%1,%2,%3}, {%4,%5,%6,%7}, {%8,%9}, {%0,%1,%2,%3};" \
        : "+f"((c)[0]), "+f"((c)[1]), "+f"((c)[2]), "+f"((c)[3]) \
        : "r"(a0), "r"(a1), "r"(a2), "r"(a3), "r"(b0), "r"(b1))

// ldmatrix x4: 4 8x8 b16 tiles; per-lane address selects tile row.
#define LDSM4(r, addr) \
    asm volatile("ldmatrix.sync.aligned.m8n8.x4.shared.b16 {%0,%1,%2,%3}, [%4];" \
        : "=r"((r)[0]), "=r"((r)[1]), "=r"((r)[2]), "=r"((r)[3]) : "r"(addr))

__device__ __forceinline__ uint32_t pack_h2(float lo, float hi) {
    __half2 h = __floats2half2_rn(lo, hi);
    return *reinterpret_cast<uint32_t*>(&h);
}

// ---------------------------------------------------------------------------
// fp32 -> fp16 conversion (n multiple of 4)
// ---------------------------------------------------------------------------
__global__ __launch_bounds__(256)
void f2h(const float* __restrict__ in, __half* __restrict__ out, int n)
{
    int i = (blockIdx.x * 256 + threadIdx.x) * 4;
    if (i < n) {
        float4 v = *(const float4*)(in + i);
        *(__half2*)(out + i)     = __floats2half2_rn(v.x, v.y);
        *(__half2*)(out + i + 2) = __floats2half2_rn(v.z, v.w);
    }
}

// ---------------------------------------------------------------------------
// fp16 mma.sync GEMM:  C[M,N] = A[M,K] @ B[N,K]^T
// Tile 128x128, BK=64 halves, 256 threads (8 warps 2m x 4n, 64x32 each),
// 3-stage cp.async pipeline, ldmatrix.x4 fragment loads.
// EPI: 0 = fp16, 1 = fp16*0.125, 2 = fp16 V^T store, 3 = GELU->fp16, 4 = fp32
// ---------------------------------------------------------------------------
#define HSTR  72                     // halves per smem row (64 + 8 pad)
#define HTILE (128 * HSTR)
#define NSTAGE 3
#define GEMMH_SMEM (2 * NSTAGE * HTILE * 2)   // 110592 B

template <int EPI>
__global__ __launch_bounds__(256)
void gemm_h(const __half* __restrict__ A, const __half* __restrict__ B,
            void* __restrict__ Cv, int M, int N, int K)
{
    extern __shared__ __half hsm[];
    uint32_t sA_u[NSTAGE], sB_u[NSTAGE];
#pragma unroll
    for (int s = 0; s < NSTAGE; s++) {
        sA_u[s] = smem_u32(hsm + s * HTILE);
        sB_u[s] = smem_u32(hsm + (NSTAGE + s) * HTILE);
    }

    const int tid = threadIdx.x;
    const int wid = tid >> 5;
    const int lid = tid & 31;
    const int gid = lid >> 2;
    const int tig = lid & 3;
    const int wm0 = (wid & 1) * 64;
    const int wn0 = (wid >> 1) * 32;
    const int bm  = blockIdx.y * 128;
    const int bn  = blockIdx.x * 128;

    const int ldRow = tid >> 3;
    const int ldC8  = (tid & 7) << 3;

    // ldmatrix lane->row mapping
    const int a_moff = (lid & 7) + ((lid >> 3) & 1) * 8;   // tiles: m0-7,m8-15,...
    const int a_koff = (lid >> 4) * 8;                     // ...k0-7 then k8-15
    const int b_noff = (lid & 7) + ((lid >> 4) & 1) * 8;   // tiles: n, k then n+8
    const int b_koff = ((lid >> 3) & 1) * 8;

    const __half* Ab = A + (size_t)bm * K;
    const __half* Bb = B + (size_t)bn * K;

    float acc[4][4][4];
#pragma unroll
    for (int i = 0; i < 4; i++)
#pragma unroll
        for (int j = 0; j < 4; j++)
#pragma unroll
            for (int r = 0; r < 4; r++) acc[i][j][r] = 0.f;

    const int KT = K >> 6;

    auto load_tile = [&](int kt, int buf) {
        const __half* Ak = Ab + (size_t)kt * 64;
        const __half* Bk = Bb + (size_t)kt * 64;
#pragma unroll
        for (int it = 0; it < 4; it++) {
            int row = ldRow + it * 32;
            uint32_t so = (uint32_t)(row * HSTR + ldC8) * 2u;
            CP_ASYNC16(sA_u[buf] + so, Ak + (size_t)row * K + ldC8);
            CP_ASYNC16(sB_u[buf] + so, Bk + (size_t)row * K + ldC8);
        }
        CP_COMMIT();
    };

    load_tile(0, 0);
    load_tile(1, 1);

    for (int kt = 0; kt < KT; kt++) {
        const int buf = kt % NSTAGE;
        if (kt + 2 < KT) {
            load_tile(kt + 2, (kt + 2) % NSTAGE);
            CP_WAIT(2);
        } else if (kt + 1 < KT) {
            CP_WAIT(1);
        } else {
            CP_WAIT(0);
        }
        __syncthreads();

        const uint32_t aB = sA_u[buf] +
            (uint32_t)((wm0 + a_moff) * HSTR + a_koff) * 2u;
        const uint32_t bB = sB_u[buf] +
            (uint32_t)((wn0 + b_noff) * HSTR + b_koff) * 2u;

#pragma unroll
        for (int ks = 0; ks < 4; ks++) {
            uint32_t a[4][4], b[2][4];
#pragma unroll
            for (int fm = 0; fm < 4; fm++)
                LDSM4(a[fm], aB + (uint32_t)(fm * 16 * HSTR) * 2u + ks * 32);
#pragma unroll
            for (int fn2 = 0; fn2 < 2; fn2++)
                LDSM4(b[fn2], bB + (uint32_t)(fn2 * 16 * HSTR) * 2u + ks * 32);
#pragma unroll
            for (int fm = 0; fm < 4; fm++)
#pragma unroll
                for (int fn = 0; fn < 4; fn++)
                    MMA_F16(acc[fm][fn],
                            a[fm][0], a[fm][1], a[fm][2], a[fm][3],
                            b[fn >> 1][(fn & 1) * 2], b[fn >> 1][(fn & 1) * 2 + 1]);
        }
        __syncthreads();
    }

    // --- epilogue ---
#pragma unroll
    for (int fm = 0; fm < 4; fm++) {
#pragma unroll
        for (int fn = 0; fn < 4; fn++) {
            float v[4];
#pragma unroll
            for (int r = 0; r < 4; r++) {
                float t = acc[fm][fn][r];
                if (EPI == 1) t *= 0.125f;
                if (EPI == 3) t = 0.5f * t * (1.f + erff(t * 0.70710678118654752f));
                v[r] = t;
            }
            const int row0 = bm + wm0 + fm * 16 + gid;
            const int col  = bn + wn0 + fn * 8 + tig * 2;
            if (EPI == 4) {
                float* C = (float*)Cv;
                *(float2*)(C + (size_t)row0 * N + col)       = make_float2(v[0], v[1]);
                *(float2*)(C + (size_t)(row0 + 8) * N + col) = make_float2(v[2], v[3]);
            } else if (EPI == 2) {
                __half* C = (__half*)Cv;
#pragma unroll
                for (int ri = 0; ri < 2; ri++) {
#pragma unroll
                    for (int ci = 0; ci < 2; ci++) {
                        int r = row0 + ri * 8;
                        int c = col + ci;
                        int bb = r >> 11, ss = r & 2047;
                        int hh = c >> 6,  dd = c & 63;
                        C[(((size_t)(bb * 16 + hh)) * 64 + dd) * SEQ + ss] =
                            __float2half(v[ri * 2 + ci]);
                    }
                }
            } else {
                __half* C = (__half*)Cv;
                *(__half2*)(C + (size_t)row0 * N + col) =
                    __floats2half2_rn(v[0], v[1]);
                *(__half2*)(C + (size_t)(row0 + 8) * N + col) =
                    __floats2half2_rn(v[2], v[3]);
            }
        }
    }
}

// ---------------------------------------------------------------------------
// Flash attention, fp16 mma.sync + ldmatrix; Q fragments persistent in regs.
// CTA = 128 queries of one (b,h); 8 warps each own 16 query rows.
// ---------------------------------------------------------------------------
#define FQS 72
#define FLASHH_SMEM ((128 * FQS + 4 * 64 * FQS) * 2)   // 55296 B

__global__ __launch_bounds__(256)
void flash_h(const __half* __restrict__ Q, const __half* __restrict__ K,
             const __half* __restrict__ Vt, __half* __restrict__ Oa)
{
    extern __shared__ __half fsh[];
    __half* Qs = fsh;                                   // [128][FQS]
    const uint32_t qs_u = smem_u32(Qs);
    const uint32_t ks_u[2] = { smem_u32(Qs + 128 * FQS),
                               smem_u32(Qs + 128 * FQS + 64 * FQS) };
    const uint32_t vs_u[2] = { smem_u32(Qs + 128 * FQS + 2 * 64 * FQS),
                               smem_u32(Qs + 128 * FQS + 3 * 64 * FQS) };

    const int tid = threadIdx.x;
    const int wid = tid >> 5;
    const int lid = tid & 31;
    const int gid = lid >> 2;
    const int tig = lid & 3;
    const int q0  = blockIdx.x * 128;
    const int bh  = blockIdx.y;
    const int b   = bh >> 4;
    const int h   = bh & 15;
    const int m0  = wid * 16;

    const int a_moff = (lid & 7) + ((lid >> 3) & 1) * 8;
    const int a_koff = (lid >> 4) * 8;
    const int b_noff = (lid & 7) + ((lid >> 4) & 1) * 8;
    const int b_koff = ((lid >> 3) & 1) * 8;

    const size_t base = (size_t)b * SEQ * DMODEL + h * DK;
    const __half* Qb = Q + base;
    const __half* Kb = K + base;
    const __half* Vb = Vt + ((size_t)(b * 16 + h)) * 64 * SEQ;
    __half*       Ob = Oa + base;

    // ---- Q tile cp.async (own group) ----
#pragma unroll
    for (int it = 0; it < 4; it++) {
        int s   = tid + it * 256;
        int row = s >> 3;
        int c8  = (s & 7) << 3;
        CP_ASYNC16(qs_u + (uint32_t)(row * FQS + c8) * 2u,
                   Qb + (size_t)(q0 + row) * DMODEL + c8);
    }
    CP_COMMIT();

    auto load_kv = [&](int kt, int buf) {
        const __half* Kt  = Kb + (size_t)kt * 64 * DMODEL;
        const __half* Vtt = Vb + kt * 64;
#pragma unroll
        for (int it = 0; it < 2; it++) {
            int s   = tid + it * 256;
            int row = s >> 3;
            int c8  = (s & 7) << 3;
            CP_ASYNC16(ks_u[buf] + (uint32_t)(row * FQS + c8) * 2u,
                       Kt + (size_t)row * DMODEL + c8);
            CP_ASYNC16(vs_u[buf] + (uint32_t)(row * FQS + c8) * 2u,
                       Vtt + (size_t)row * SEQ + c8);
        }
        CP_COMMIT();
    };

    load_kv(0, 0);

    // ---- hoist Q fragments into registers (wait: Q done, kv0 may pend) ----
    CP_WAIT(1);
    __syncthreads();
    uint32_t qf[4][4];
    {
        const uint32_t qB = qs_u + (uint32_t)((m0 + a_moff) * FQS + a_koff) * 2u;
#pragma unroll
        for (int kf = 0; kf < 4; kf++)
            LDSM4(qf[kf], qB + kf * 32);
    }

    float m[2] = { -1e30f, -1e30f };
    float l[2] = { 0.f, 0.f };
    float o[8][4];
#pragma unroll
    for (int d = 0; d < 8; d++)
#pragma unroll
        for (int r = 0; r < 4; r++) o[d][r] = 0.f;

    const int NT = SEQ / 64;

    for (int kt = 0; kt < NT; kt++) {
        const int buf = kt & 1;
        if (kt + 1 < NT) { load_kv(kt + 1, buf ^ 1); CP_WAIT(1); }
        else             { CP_WAIT(0); }
        __syncthreads();

        const uint32_t kB = ks_u[buf] + (uint32_t)(b_noff * FQS + b_koff) * 2u;
        const uint32_t vB = vs_u[buf] + (uint32_t)(b_noff * FQS + b_koff) * 2u;

        // ---- S = Q @ K^T : warp [16, 64] ----
        float s[8][4];
#pragma unroll
        for (int nf = 0; nf < 8; nf++)
#pragma unroll
            for (int r = 0; r < 4; r++) s[nf][r] = 0.f;

#pragma unroll
        for (int kf = 0; kf < 4; kf++) {
#pragma unroll
            for (int fn2 = 0; fn2 < 4; fn2++) {
                uint32_t kb[4];
                LDSM4(kb, kB + (uint32_t)(fn2 * 16 * FQS) * 2u + kf * 32);
                MMA_F16(s[2 * fn2],     qf[kf][0], qf[kf][1], qf[kf][2], qf[kf][3],
                        kb[0], kb[1]);
                MMA_F16(s[2 * fn2 + 1], qf[kf][0], qf[kf][1], qf[kf][2], qf[kf][3],
                        kb[2], kb[3]);
            }
        }

        // ---- online softmax ----
        float mx0 = -1e30f, mx1 = -1e30f;
#pragma unroll
        for (int nf = 0; nf < 8; nf++) {
            mx0 = fmaxf(mx0, fmaxf(s[nf][0], s[nf][1]));
            mx1 = fmaxf(mx1, fmaxf(s[nf][2], s[nf][3]));
        }
        mx0 = fmaxf(mx0, __shfl_xor_sync(0xffffffffu, mx0, 1));
        mx0 = fmaxf(mx0, __shfl_xor_sync(0xffffffffu, mx0, 2));
        mx1 = fmaxf(mx1, __shfl_xor_sync(0xffffffffu, mx1, 1));
        mx1 = fmaxf(mx1, __shfl_xor_sync(0xffffffffu, mx1, 2));

        const float mn0 = fmaxf(m[0], mx0);
        const float mn1 = fmaxf(m[1], mx1);
        const float al0 = __expf(m[0] - mn0);
        const float al1 = __expf(m[1] - mn1);

        float sum0 = 0.f, sum1 = 0.f;
#pragma unroll
        for (int nf = 0; nf < 8; nf++) {
            s[nf][0] = __expf(s[nf][0] - mn0);
            s[nf][1] = __expf(s[nf][1] - mn0);
            s[nf][2] = __expf(s[nf][2] - mn1);
            s[nf][3] = __expf(s[nf][3] - mn1);
            sum0 += s[nf][0] + s[nf][1];
            sum1 += s[nf][2] + s[nf][3];
        }
        sum0 += __shfl_xor_sync(0xffffffffu, sum0, 1);
        sum0 += __shfl_xor_sync(0xffffffffu, sum0, 2);
        sum1 += __shfl_xor_sync(0xffffffffu, sum1, 1);
        sum1 += __shfl_xor_sync(0xffffffffu, sum1, 2);

        l[0] = l[0] * al0 + sum0;
        l[1] = l[1] * al1 + sum1;
        m[0] = mn0;
        m[1] = mn1;

#pragma unroll
        for (int d = 0; d < 8; d++) {
            o[d][0] *= al0; o[d][1] *= al0;
            o[d][2] *= al1; o[d][3] *= al1;
        }

        // ---- O += P @ V ----
#pragma unroll
        for (int c = 0; c < 4; c++) {
            uint32_t a0 = pack_h2(s[2*c][0],   s[2*c][1]);
            uint32_t a1 = pack_h2(s[2*c][2],   s[2*c][3]);
            uint32_t a2 = pack_h2(s[2*c+1][0], s[2*c+1][1]);
            uint32_t a3 = pack_h2(s[2*c+1][2], s[2*c+1][3]);
#pragma unroll
            for (int fn2 = 0; fn2 < 4; fn2++) {
                uint32_t vb[4];
                LDSM4(vb, vB + (uint32_t)(fn2 * 16 * FQS) * 2u + c * 32);
                MMA_F16(o[2 * fn2],     a0, a1, a2, a3, vb[0], vb[1]);
                MMA_F16(o[2 * fn2 + 1], a0, a1, a2, a3, vb[2], vb[3]);
            }
        }
        __syncthreads();
    }

    // ---- epilogue: O / l -> fp16 ----
    const float inv0 = 1.f / l[0];
    const float inv1 = 1.f / l[1];
    const int row0 = q0 + m0 + gid;
#pragma unroll
    for (int d = 0; d < 8; d++) {
        const int col = d * 8 + tig * 2;
        *(__half2*)(Ob + (size_t)row0 * DMODEL + col) =
            __floats2half2_rn(o[d][0] * inv0, o[d][1] * inv0);
        *(__half2*)(Ob + (size_t)(row0 + 8) * DMODEL + col) =
            __floats2half2_rn(o[d][2] * inv1, o[d][3] * inv1);
    }
}

// ---------------------------------------------------------------------------
// y = LayerNorm(a + b) * gamma + beta; dual output (fp32 + fp16)
// ---------------------------------------------------------------------------
__global__ __launch_bounds__(256)
void add_ln2(const float* __restrict__ a, const float* __restrict__ b,
             const float* __restrict__ gamma, const float* __restrict__ beta,
             float* __restrict__ y, __half* __restrict__ yh)
{
    const int row = blockIdx.x;
    const int tid = threadIdx.x;
    __shared__ float rs[256], rq[256];

    float4 va = ((const float4*)(a + (size_t)row * DMODEL))[tid];
    float4 vb = ((const float4*)(b + (size_t)row * DMODEL))[tid];
    float s0 = va.x + vb.x, s1 = va.y + vb.y, s2 = va.z + vb.z, s3 = va.w + vb.w;

    rs[tid] = s0 + s1 + s2 + s3;
    rq[tid] = s0 * s0 + s1 * s1 + s2 * s2 + s3 * s3;
    __syncthreads();
#pragma unroll
    for (int off = 128; off > 0; off >>= 1) {
        if (tid < off) { rs[tid] += rs[tid + off]; rq[tid] += rq[tid + off]; }
        __syncthreads();
    }
    const float mu   = rs[0] * (1.f / DMODEL);
    const float var  = rq[0] * (1.f / DMODEL) - mu * mu;
    const float rinv = rsqrtf(var + 1e-5f);

    float4 g  = ((const float4*)gamma)[tid];
    float4 be = ((const float4*)beta)[tid];
    float4 out;
    out.x = (s0 - mu) * rinv * g.x + be.x;
    out.y = (s1 - mu) * rinv * g.y + be.y;
    out.z = (s2 - mu) * rinv * g.z + be.z;
    out.w = (s3 - mu) * rinv * g.w + be.w;
    ((float4*)(y + (size_t)row * DMODEL))[tid] = out;

    __half* hp = yh + (size_t)row * DMODEL + tid * 4;
    *(__half2*)(hp)     = __floats2half2_rn(out.x, out.y);
    *(__half2*)(hp + 2) = __floats2half2_rn(out.z, out.w);
}

// ---------------------------------------------------------------------------
// launch
// ---------------------------------------------------------------------------
extern "C" void kernel_launch(void* const* d_in, const int* in_sizes, int n_in,
                              void* d_out, int out_size)
{
    const float* x  = (const float*)d_in[0];
    const float* Wq = (const float*)d_in[1];
    const float* Wk = (const float*)d_in[2];
    const float* Wv = (const float*)d_in[3];
    const float* Wo = (const float*)d_in[4];
    const float* W1 = (const float*)d_in[5];
    const float* W2 = (const float*)d_in[6];
    const float* g1 = (const float*)d_in[7];
    const float* b1 = (const float*)d_in[8];
    const float* g2 = (const float*)d_in[9];
    const float* b2 = (const float*)d_in[10];
    float* out = (float*)d_out;

    __half *px, *pwq, *pwk, *pwv, *pwo, *pw1, *pw2;
    __half *pq, *pk, *pvt, *pattn, *px1h, *pff;
    float *pproj, *px1;
    cudaGetSymbolAddress((void**)&px,   hx);
    cudaGetSymbolAddress((void**)&pwq,  hWq);
    cudaGetSymbolAddress((void**)&pwk,  hWk);
    cudaGetSymbolAddress((void**)&pwv,  hWv);
    cudaGetSymbolAddress((void**)&pwo,  hWo);
    cudaGetSymbolAddress((void**)&pw1,  hW1);
    cudaGetSymbolAddress((void**)&pw2,  hW2);
    cudaGetSymbolAddress((void**)&pq,   hq);
    cudaGetSymbolAddress((void**)&pk,   hk);
    cudaGetSymbolAddress((void**)&pvt,  hvt);
    cudaGetSymbolAddress((void**)&pattn,hattn);
    cudaGetSymbolAddress((void**)&px1h, hx1);
    cudaGetSymbolAddress((void**)&pff,  hff);
    cudaGetSymbolAddress((void**)&pproj,g_proj);
    cudaGetSymbolAddress((void**)&px1,  g_x1);

    cudaFuncSetAttribute(gemm_h<0>, cudaFuncAttributeMaxDynamicSharedMemorySize, GEMMH_SMEM);
    cudaFuncSetAttribute(gemm_h<1>, cudaFuncAttributeMaxDynamicSharedMemorySize, GEMMH_SMEM);
    cudaFuncSetAttribute(gemm_h<2>, cudaFuncAttributeMaxDynamicSharedMemorySize, GEMMH_SMEM);
    cudaFuncSetAttribute(gemm_h<3>, cudaFuncAttributeMaxDynamicSharedMemorySize, GEMMH_SMEM);
    cudaFuncSetAttribute(gemm_h<4>, cudaFuncAttributeMaxDynamicSharedMemorySize, GEMMH_SMEM);
    cudaFuncSetAttribute(flash_h,   cudaFuncAttributeMaxDynamicSharedMemorySize, FLASHH_SMEM);

    // ---- fp32 -> fp16 conversions ----
    auto cv = [&](const float* src, __half* dst, int n) {
        f2h<<<n / 1024, 256>>>(src, dst, n);
    };
    cv(x,  px,  TOKENS * DMODEL);
    cv(Wq, pwq, DMODEL * DMODEL);
    cv(Wk, pwk, DMODEL * DMODEL);
    cv(Wv, pwv, DMODEL * DMODEL);
    cv(Wo, pwo, DMODEL * DMODEL);
    cv(W1, pw1, DFF * DMODEL);
    cv(W2, pw2, DMODEL * DFF);

    dim3 blk(256);
    dim3 gqkv(DMODEL / 128, TOKENS / 128);

    // QKV projections (Q pre-scaled, V stored transposed)
    gemm_h<1><<<gqkv, blk, GEMMH_SMEM>>>(px, pwq, pq,  TOKENS, DMODEL, DMODEL);
    gemm_h<0><<<gqkv, blk, GEMMH_SMEM>>>(px, pwk, pk,  TOKENS, DMODEL, DMODEL);
    gemm_h<2><<<gqkv, blk, GEMMH_SMEM>>>(px, pwv, pvt, TOKENS, DMODEL, DMODEL);

    // attention
    dim3 gattn(SEQ / 128, 2 * NHEADS);
    flash_h<<<gattn, blk, FLASHH_SMEM>>>(pq, pk, pvt, pattn);

    // output projection + residual + LN1
    gemm_h<4><<<gqkv, blk, GEMMH_SMEM>>>(pattn, pwo, pproj, TOKENS, DMODEL, DMODEL);
    add_ln2<<<TOKENS, 256>>>(x, pproj, g1, b1, px1, px1h);

    // FF1 (+GELU), FF2, residual + LN2
    dim3 gff1(DFF / 128, TOKENS / 128);
    gemm_h<3><<<gff1, blk, GEMMH_SMEM>>>(px1h, pw1, pff,  TOKENS, DFF, DMODEL);
    gemm_h<4><<<gqkv, blk, GEMMH_SMEM>>>(pff, pw2, pproj, TOKENS, DMODEL, DFF);
    add_ln2<<<TOKENS, 256>>>(px1, pproj, g2, b2, out, px1h);
}

// round 7
// speedup vs baseline: 6.9580x; 1.0236x over previous
#include <cuda_runtime.h>
#include <cuda_fp16.h>
#include <math.h>
#include <cstdint>

// ---------------------------------------------------------------------------
// Problem constants
// ---------------------------------------------------------------------------
#define TOKENS 4096        // B*S = 2*2048
#define DMODEL 1024
#define DFF    4096
#define NHEADS 16
#define DK     64
#define SEQ    2048

// ---------------------------------------------------------------------------
// Scratch (device globals)
// ---------------------------------------------------------------------------
__device__ __half hx   [TOKENS * DMODEL];
__device__ __half hWq  [DMODEL * DMODEL];
__device__ __half hWk  [DMODEL * DMODEL];
__device__ __half hWv  [DMODEL * DMODEL];
__device__ __half hWo  [DMODEL * DMODEL];
__device__ __half hW1  [DFF * DMODEL];
__device__ __half hW2  [DMODEL * DFF];
__device__ __half hq   [TOKENS * DMODEL];   // pre-scaled by 1/8
__device__ __half hk   [TOKENS * DMODEL];
__device__ __half hvt  [TOKENS * DMODEL];   // V transposed: [b][h][d][s]
__device__ __half hattn[TOKENS * DMODEL];
__device__ __half hx1  [TOKENS * DMODEL];
__device__ __half hff  [TOKENS * DFF];
__device__ float  g_proj[TOKENS * DMODEL];
__device__ float  g_x1 [TOKENS * DMODEL];

// ---------------------------------------------------------------------------
// Helpers
// ---------------------------------------------------------------------------
__device__ __forceinline__ uint32_t smem_u32(const void* p) {
    uint32_t a;
    asm("{ .reg .u64 t; cvta.to.shared.u64 t, %1; cvt.u32.u64 %0, t; }"
        : "=r"(a) : "l"(p));
    return a;
}

#define CP_ASYNC16(dst_u32, src_ptr) \
    asm volatile("cp.async.cg.shared.global [%0], [%1], 16;" \
        :: "r"(dst_u32), "l"(src_ptr))
#define CP_COMMIT() asm volatile("cp.async.commit_group;")
#define CP_WAIT(n)  asm volatile("cp.async.wait_group %0;" :: "n"(n))

#define MMA_F16(c, a0, a1, a2, a3, b0, b1) \
    asm volatile("mma.sync.aligned.m16n8k16.row.col.f32.f16.f16.f32 " \
        "{%0,%1,%2,%3}, {%4,%5,%6,%7}, {%8,%9}, {%0,%1,%2,%3};" \
        : "+f"((c)[0]), "+f"((c)[1]), "+f"((c)[2]), "+f"((c)[3]) \
        : "r"(a0), "r"(a1), "r"(a2), "r"(a3), "r"(b0), "r"(b1))

#define LDSM4(r, addr) \
    asm volatile("ldmatrix.sync.aligned.m8n8.x4.shared.b16 {%0,%1,%2,%3}, [%4];" \
        : "=r"((r)[0]), "=r"((r)[1]), "=r"((r)[2]), "=r"((r)[3]) : "r"(addr))

__device__ __forceinline__ uint32_t pack_h2(float lo, float hi) {
    __half2 h = __floats2half2_rn(lo, hi);
    return *reinterpret_cast<uint32_t*>(&h);
}

// ---------------------------------------------------------------------------
// fp32 -> fp16 conversion, all tensors in one launch (grid.y selects tensor)
// ---------------------------------------------------------------------------
__global__ __launch_bounds__(256)
void f2h_all(const float* x,  __half* dx,
             const float* w0, __half* d0, const float* w1, __half* d1,
             const float* w2, __half* d2, const float* w3, __half* d3,
             const float* w4, __half* d4, const float* w5, __half* d5)
{
    const float* src; __half* dst; int n;
    switch (blockIdx.y) {
        case 0: src = x;  dst = dx; n = TOKENS * DMODEL; break;
        case 1: src = w0; dst = d0; n = DMODEL * DMODEL; break;
        case 2: src = w1; dst = d1; n = DMODEL * DMODEL; break;
        case 3: src = w2; dst = d2; n = DMODEL * DMODEL; break;
        case 4: src = w3; dst = d3; n = DMODEL * DMODEL; break;
        case 5: src = w4; dst = d4; n = DFF * DMODEL;    break;
        default:src = w5; dst = d5; n = DMODEL * DFF;    break;
    }
    int i = (blockIdx.x * 256 + threadIdx.x) * 4;
    if (i < n) {
        float4 v = *(const float4*)(src + i);
        *(__half2*)(dst + i)     = __floats2half2_rn(v.x, v.y);
        *(__half2*)(dst + i + 2) = __floats2half2_rn(v.z, v.w);
    }
}

// ---------------------------------------------------------------------------
// 128(M) x 256(N) x BK=64 fp16 GEMM pieces (shared via macros)
// 256 threads, 8 warps (2m x 4n), each warp 64x64. 2-stage cp.async.
// ---------------------------------------------------------------------------
#define HSTR   72
#define ATILE  (128 * HSTR)
#define BTILE  (256 * HSTR)
#define GEMM2_SMEM ((2 * ATILE + 2 * BTILE) * 2)   // 110592 B

#define GEMM_IDS \
    const int tid = threadIdx.x; \
    const int wid = tid >> 5; \
    const int lid = tid & 31; \
    const int gid = lid >> 2; \
    const int tig = lid & 3; \
    const int wm0 = (wid & 1) * 64; \
    const int wn0 = (wid >> 1) * 64; \
    const int ldRow = tid >> 3; \
    const int ldC8  = (tid & 7) << 3; \
    const int a_moff = (lid & 7) + ((lid >> 3) & 1) * 8; \
    const int a_koff = (lid >> 4) * 8; \
    const int b_noff = (lid & 7) + ((lid >> 4) & 1) * 8; \
    const int b_koff = ((lid >> 3) & 1) * 8;

#define GEMM_SMEM_PTRS \
    extern __shared__ __half hsm[]; \
    uint32_t sA_u[2], sB_u[2]; \
    sA_u[0] = smem_u32(hsm);             sA_u[1] = smem_u32(hsm + ATILE); \
    sB_u[0] = smem_u32(hsm + 2 * ATILE); sB_u[1] = smem_u32(hsm + 2 * ATILE + BTILE);

#define GEMM_LOAD_TILE(kt, buf, Ab, Bb, K) do { \
    const __half* Ak_ = (Ab) + (size_t)(kt) * 64; \
    const __half* Bk_ = (Bb) + (size_t)(kt) * 64; \
    _Pragma("unroll") \
    for (int it = 0; it < 4; it++) { \
        int row = ldRow + it * 32; \
        CP_ASYNC16(sA_u[buf] + (uint32_t)(row * HSTR + ldC8) * 2u, \
                   Ak_ + (size_t)row * (K) + ldC8); \
    } \
    _Pragma("unroll") \
    for (int it = 0; it < 8; it++) { \
        int row = ldRow + it * 32; \
        CP_ASYNC16(sB_u[buf] + (uint32_t)(row * HSTR + ldC8) * 2u, \
                   Bk_ + (size_t)row * (K) + ldC8); \
    } \
    CP_COMMIT(); \
} while (0)

#define GEMM_COMPUTE_TILE(buf, acc) do { \
    const uint32_t aB_ = sA_u[buf] + (uint32_t)((wm0 + a_moff) * HSTR + a_koff) * 2u; \
    const uint32_t bB_ = sB_u[buf] + (uint32_t)((wn0 + b_noff) * HSTR + b_koff) * 2u; \
    _Pragma("unroll") \
    for (int ks = 0; ks < 4; ks++) { \
        uint32_t a[4][4], b[4][4]; \
        _Pragma("unroll") \
        for (int fm = 0; fm < 4; fm++) \
            LDSM4(a[fm], aB_ + (uint32_t)(fm * 16 * HSTR) * 2u + ks * 32); \
        _Pragma("unroll") \
        for (int fn2 = 0; fn2 < 4; fn2++) \
            LDSM4(b[fn2], bB_ + (uint32_t)(fn2 * 16 * HSTR) * 2u + ks * 32); \
        _Pragma("unroll") \
        for (int fm = 0; fm < 4; fm++) \
            _Pragma("unroll") \
            for (int fn = 0; fn < 8; fn++) \
                MMA_F16(acc[fm][fn], \
                        a[fm][0], a[fm][1], a[fm][2], a[fm][3], \
                        b[fn >> 1][(fn & 1) * 2], b[fn >> 1][(fn & 1) * 2 + 1]); \
    } \
} while (0)

// ---------------------------------------------------------------------------
// General GEMM:  C[M,N] = A[M,K] @ B[N,K]^T
// EPI: 0 = fp16, 3 = exact GELU -> fp16, 4 = fp32
// ---------------------------------------------------------------------------
template <int EPI>
__global__ __launch_bounds__(256)
void gemm256(const __half* __restrict__ A, const __half* __restrict__ B,
             void* __restrict__ Cv, int M, int N, int K)
{
    GEMM_SMEM_PTRS
    GEMM_IDS
    const int bm = blockIdx.y * 128;
    const int bn = blockIdx.x * 256;

    const __half* Ab = A + (size_t)bm * K;
    const __half* Bb = B + (size_t)bn * K;

    float acc[4][8][4];
#pragma unroll
    for (int i = 0; i < 4; i++)
#pragma unroll
        for (int j = 0; j < 8; j++)
#pragma unroll
            for (int r = 0; r < 4; r++) acc[i][j][r] = 0.f;

    const int KT = K >> 6;
    GEMM_LOAD_TILE(0, 0, Ab, Bb, K);

    for (int kt = 0; kt < KT; kt++) {
        const int buf = kt & 1;
        if (kt + 1 < KT) { GEMM_LOAD_TILE(kt + 1, buf ^ 1, Ab, Bb, K); CP_WAIT(1); }
        else             { CP_WAIT(0); }
        __syncthreads();
        GEMM_COMPUTE_TILE(buf, acc);
        __syncthreads();
    }

#pragma unroll
    for (int fm = 0; fm < 4; fm++) {
#pragma unroll
        for (int fn = 0; fn < 8; fn++) {
            float v[4];
#pragma unroll
            for (int r = 0; r < 4; r++) {
                float t = acc[fm][fn][r];
                if (EPI == 3) t = 0.5f * t * (1.f + erff(t * 0.70710678118654752f));
                v[r] = t;
            }
            const int row0 = bm + wm0 + fm * 16 + gid;
            const int col  = bn + wn0 + fn * 8 + tig * 2;
            if (EPI == 4) {
                float* C = (float*)Cv;
                *(float2*)(C + (size_t)row0 * N + col)       = make_float2(v[0], v[1]);
                *(float2*)(C + (size_t)(row0 + 8) * N + col) = make_float2(v[2], v[3]);
            } else {
                __half* C = (__half*)Cv;
                *(__half2*)(C + (size_t)row0 * N + col) =
                    __floats2half2_rn(v[0], v[1]);
                *(__half2*)(C + (size_t)(row0 + 8) * N + col) =
                    __floats2half2_rn(v[2], v[3]);
            }
        }
    }
}

// ---------------------------------------------------------------------------
// Fused QKV GEMM. grid.x = 12: weight w = blockIdx.x >> 2,
// bn = (blockIdx.x & 3) * 256. Epilogue: w=0 Q*0.125, w=1 K plain, w=2 V^T.
// ---------------------------------------------------------------------------
__global__ __launch_bounds__(256)
void gemm_qkv(const __half* __restrict__ A,
              const __half* __restrict__ Bq, const __half* __restrict__ Bk,
              const __half* __restrict__ Bv,
              __half* __restrict__ Cq, __half* __restrict__ Ck,
              __half* __restrict__ Cvt)
{
    GEMM_SMEM_PTRS
    GEMM_IDS
    const int K  = DMODEL;
    const int w  = blockIdx.x >> 2;
    const int bn = (blockIdx.x & 3) * 256;
    const int bm = blockIdx.y * 128;

    const __half* Bsel = (w == 0) ? Bq : (w == 1) ? Bk : Bv;
    const __half* Ab = A + (size_t)bm * K;
    const __half* Bb = Bsel + (size_t)bn * K;

    float acc[4][8][4];
#pragma unroll
    for (int i = 0; i < 4; i++)
#pragma unroll
        for (int j = 0; j < 8; j++)
#pragma unroll
            for (int r = 0; r < 4; r++) acc[i][j][r] = 0.f;

    const int KT = K >> 6;
    GEMM_LOAD_TILE(0, 0, Ab, Bb, K);

    for (int kt = 0; kt < KT; kt++) {
        const int buf = kt & 1;
        if (kt + 1 < KT) { GEMM_LOAD_TILE(kt + 1, buf ^ 1, Ab, Bb, K); CP_WAIT(1); }
        else             { CP_WAIT(0); }
        __syncthreads();
        GEMM_COMPUTE_TILE(buf, acc);
        __syncthreads();
    }

#pragma unroll
    for (int fm = 0; fm < 4; fm++) {
#pragma unroll
        for (int fn = 0; fn < 8; fn++) {
            const int row0 = bm + wm0 + fm * 16 + gid;
            const int col  = bn + wn0 + fn * 8 + tig * 2;
            float* v = acc[fm][fn];
            if (w == 0) {
                *(__half2*)(Cq + (size_t)row0 * DMODEL + col) =
                    __floats2half2_rn(v[0] * 0.125f, v[1] * 0.125f);
                *(__half2*)(Cq + (size_t)(row0 + 8) * DMODEL + col) =
                    __floats2half2_rn(v[2] * 0.125f, v[3] * 0.125f);
            } else if (w == 1) {
                *(__half2*)(Ck + (size_t)row0 * DMODEL + col) =
                    __floats2half2_rn(v[0], v[1]);
                *(__half2*)(Ck + (size_t)(row0 + 8) * DMODEL + col) =
                    __floats2half2_rn(v[2], v[3]);
            } else {
#pragma unroll
                for (int ri = 0; ri < 2; ri++) {
#pragma unroll
                    for (int ci = 0; ci < 2; ci++) {
                        int r = row0 + ri * 8;
                        int c = col + ci;
                        int bb = r >> 11, ss = r & 2047;
                        int hh = c >> 6,  dd = c & 63;
                        Cvt[(((size_t)(bb * 16 + hh)) * 64 + dd) * SEQ + ss] =
                            __float2half(v[ri * 2 + ci]);
                    }
                }
            }
        }
    }
}

// ---------------------------------------------------------------------------
// Flash attention (unchanged from R6): fp16 mma + ldmatrix, Q frags in regs.
// ---------------------------------------------------------------------------
#define FQS 72
#define FLASHH_SMEM ((128 * FQS + 4 * 64 * FQS) * 2)   // 55296 B

__global__ __launch_bounds__(256)
void flash_h(const __half* __restrict__ Q, const __half* __restrict__ K,
             const __half* __restrict__ Vt, __half* __restrict__ Oa)
{
    extern __shared__ __half fsh[];
    __half* Qs = fsh;
    const uint32_t qs_u = smem_u32(Qs);
    const uint32_t ks_u[2] = { smem_u32(Qs + 128 * FQS),
                               smem_u32(Qs + 128 * FQS + 64 * FQS) };
    const uint32_t vs_u[2] = { smem_u32(Qs + 128 * FQS + 2 * 64 * FQS),
                               smem_u32(Qs + 128 * FQS + 3 * 64 * FQS) };

    const int tid = threadIdx.x;
    const int wid = tid >> 5;
    const int lid = tid & 31;
    const int gid = lid >> 2;
    const int tig = lid & 3;
    const int q0  = blockIdx.x * 128;
    const int bh  = blockIdx.y;
    const int b   = bh >> 4;
    const int h   = bh & 15;
    const int m0  = wid * 16;

    const int a_moff = (lid & 7) + ((lid >> 3) & 1) * 8;
    const int a_koff = (lid >> 4) * 8;
    const int b_noff = (lid & 7) + ((lid >> 4) & 1) * 8;
    const int b_koff = ((lid >> 3) & 1) * 8;

    const size_t base = (size_t)b * SEQ * DMODEL + h * DK;
    const __half* Qb = Q + base;
    const __half* Kb = K + base;
    const __half* Vb = Vt + ((size_t)(b * 16 + h)) * 64 * SEQ;
    __half*       Ob = Oa + base;

#pragma unroll
    for (int it = 0; it < 4; it++) {
        int s   = tid + it * 256;
        int row = s >> 3;
        int c8  = (s & 7) << 3;
        CP_ASYNC16(qs_u + (uint32_t)(row * FQS + c8) * 2u,
                   Qb + (size_t)(q0 + row) * DMODEL + c8);
    }
    CP_COMMIT();

    auto load_kv = [&](int kt, int buf) {
        const __half* Kt  = Kb + (size_t)kt * 64 * DMODEL;
        const __half* Vtt = Vb + kt * 64;
#pragma unroll
        for (int it = 0; it < 2; it++) {
            int s   = tid + it * 256;
            int row = s >> 3;
            int c8  = (s & 7) << 3;
            CP_ASYNC16(ks_u[buf] + (uint32_t)(row * FQS + c8) * 2u,
                       Kt + (size_t)row * DMODEL + c8);
            CP_ASYNC16(vs_u[buf] + (uint32_t)(row * FQS + c8) * 2u,
                       Vtt + (size_t)row * SEQ + c8);
        }
        CP_COMMIT();
    };

    load_kv(0, 0);

    CP_WAIT(1);
    __syncthreads();
    uint32_t qf[4][4];
    {
        const uint32_t qB = qs_u + (uint32_t)((m0 + a_moff) * FQS + a_koff) * 2u;
#pragma unroll
        for (int kf = 0; kf < 4; kf++)
            LDSM4(qf[kf], qB + kf * 32);
    }

    float m[2] = { -1e30f, -1e30f };
    float l[2] = { 0.f, 0.f };
    float o[8][4];
#pragma unroll
    for (int d = 0; d < 8; d++)
#pragma unroll
        for (int r = 0; r < 4; r++) o[d][r] = 0.f;

    const int NT = SEQ / 64;

    for (int kt = 0; kt < NT; kt++) {
        const int buf = kt & 1;
        if (kt + 1 < NT) { load_kv(kt + 1, buf ^ 1); CP_WAIT(1); }
        else             { CP_WAIT(0); }
        __syncthreads();

        const uint32_t kB = ks_u[buf] + (uint32_t)(b_noff * FQS + b_koff) * 2u;
        const uint32_t vB = vs_u[buf] + (uint32_t)(b_noff * FQS + b_koff) * 2u;

        float s[8][4];
#pragma unroll
        for (int nf = 0; nf < 8; nf++)
#pragma unroll
            for (int r = 0; r < 4; r++) s[nf][r] = 0.f;

#pragma unroll
        for (int kf = 0; kf < 4; kf++) {
#pragma unroll
            for (int fn2 = 0; fn2 < 4; fn2++) {
                uint32_t kb[4];
                LDSM4(kb, kB + (uint32_t)(fn2 * 16 * FQS) * 2u + kf * 32);
                MMA_F16(s[2 * fn2],     qf[kf][0], qf[kf][1], qf[kf][2], qf[kf][3],
                        kb[0], kb[1]);
                MMA_F16(s[2 * fn2 + 1], qf[kf][0], qf[kf][1], qf[kf][2], qf[kf][3],
                        kb[2], kb[3]);
            }
        }

        float mx0 = -1e30f, mx1 = -1e30f;
#pragma unroll
        for (int nf = 0; nf < 8; nf++) {
            mx0 = fmaxf(mx0, fmaxf(s[nf][0], s[nf][1]));
            mx1 = fmaxf(mx1, fmaxf(s[nf][2], s[nf][3]));
        }
        mx0 = fmaxf(mx0, __shfl_xor_sync(0xffffffffu, mx0, 1));
        mx0 = fmaxf(mx0, __shfl_xor_sync(0xffffffffu, mx0, 2));
        mx1 = fmaxf(mx1, __shfl_xor_sync(0xffffffffu, mx1, 1));
        mx1 = fmaxf(mx1, __shfl_xor_sync(0xffffffffu, mx1, 2));

        const float mn0 = fmaxf(m[0], mx0);
        const float mn1 = fmaxf(m[1], mx1);
        const float al0 = __expf(m[0] - mn0);
        const float al1 = __expf(m[1] - mn1);

        float sum0 = 0.f, sum1 = 0.f;
#pragma unroll
        for (int nf = 0; nf < 8; nf++) {
            s[nf][0] = __expf(s[nf][0] - mn0);
            s[nf][1] = __expf(s[nf][1] - mn0);
            s[nf][2] = __expf(s[nf][2] - mn1);
            s[nf][3] = __expf(s[nf][3] - mn1);
            sum0 += s[nf][0] + s[nf][1];
            sum1 += s[nf][2] + s[nf][3];
        }
        sum0 += __shfl_xor_sync(0xffffffffu, sum0, 1);
        sum0 += __shfl_xor_sync(0xffffffffu, sum0, 2);
        sum1 += __shfl_xor_sync(0xffffffffu, sum1, 1);
        sum1 += __shfl_xor_sync(0xffffffffu, sum1, 2);

        l[0] = l[0] * al0 + sum0;
        l[1] = l[1] * al1 + sum1;
        m[0] = mn0;
        m[1] = mn1;

#pragma unroll
        for (int d = 0; d < 8; d++) {
            o[d][0] *= al0; o[d][1] *= al0;
            o[d][2] *= al1; o[d][3] *= al1;
        }

#pragma unroll
        for (int c = 0; c < 4; c++) {
            uint32_t a0 = pack_h2(s[2*c][0],   s[2*c][1]);
            uint32_t a1 = pack_h2(s[2*c][2],   s[2*c][3]);
            uint32_t a2 = pack_h2(s[2*c+1][0], s[2*c+1][1]);
            uint32_t a3 = pack_h2(s[2*c+1][2], s[2*c+1][3]);
#pragma unroll
            for (int fn2 = 0; fn2 < 4; fn2++) {
                uint32_t vb[4];
                LDSM4(vb, vB + (uint32_t)(fn2 * 16 * FQS) * 2u + c * 32);
                MMA_F16(o[2 * fn2],     a0, a1, a2, a3, vb[0], vb[1]);
                MMA_F16(o[2 * fn2 + 1], a0, a1, a2, a3, vb[2], vb[3]);
            }
        }
        __syncthreads();
    }

    const float inv0 = 1.f / l[0];
    const float inv1 = 1.f / l[1];
    const int row0 = q0 + m0 + gid;
#pragma unroll
    for (int d = 0; d < 8; d++) {
        const int col = d * 8 + tig * 2;
        *(__half2*)(Ob + (size_t)row0 * DMODEL + col) =
            __floats2half2_rn(o[d][0] * inv0, o[d][1] * inv0);
        *(__half2*)(Ob + (size_t)(row0 + 8) * DMODEL + col) =
            __floats2half2_rn(o[d][2] * inv1, o[d][3] * inv1);
    }
}

// ---------------------------------------------------------------------------
// y = LayerNorm(a + b) * gamma + beta; dual output (fp32 + fp16)
// ---------------------------------------------------------------------------
__global__ __launch_bounds__(256)
void add_ln2(const float* __restrict__ a, const float* __restrict__ b,
             const float* __restrict__ gamma, const float* __restrict__ beta,
             float* __restrict__ y, __half* __restrict__ yh)
{
    const int row = blockIdx.x;
    const int tid = threadIdx.x;
    __shared__ float rs[256], rq[256];

    float4 va = ((const float4*)(a + (size_t)row * DMODEL))[tid];
    float4 vb = ((const float4*)(b + (size_t)row * DMODEL))[tid];
    float s0 = va.x + vb.x, s1 = va.y + vb.y, s2 = va.z + vb.z, s3 = va.w + vb.w;

    rs[tid] = s0 + s1 + s2 + s3;
    rq[tid] = s0 * s0 + s1 * s1 + s2 * s2 + s3 * s3;
    __syncthreads();
#pragma unroll
    for (int off = 128; off > 0; off >>= 1) {
        if (tid < off) { rs[tid] += rs[tid + off]; rq[tid] += rq[tid + off]; }
        __syncthreads();
    }
    const float mu   = rs[0] * (1.f / DMODEL);
    const float var  = rq[0] * (1.f / DMODEL) - mu * mu;
    const float rinv = rsqrtf(var + 1e-5f);

    float4 g  = ((const float4*)gamma)[tid];
    float4 be = ((const float4*)beta)[tid];
    float4 out;
    out.x = (s0 - mu) * rinv * g.x + be.x;
    out.y = (s1 - mu) * rinv * g.y + be.y;
    out.z = (s2 - mu) * rinv * g.z + be.z;
    out.w = (s3 - mu) * rinv * g.w + be.w;
    ((float4*)(y + (size_t)row * DMODEL))[tid] = out;

    __half* hp = yh + (size_t)row * DMODEL + tid * 4;
    *(__half2*)(hp)     = __floats2half2_rn(out.x, out.y);
    *(__half2*)(hp + 2) = __floats2half2_rn(out.z, out.w);
}

// ---------------------------------------------------------------------------
// launch
// ---------------------------------------------------------------------------
extern "C" void kernel_launch(void* const* d_in, const int* in_sizes, int n_in,
                              void* d_out, int out_size)
{
    const float* x  = (const float*)d_in[0];
    const float* Wq = (const float*)d_in[1];
    const float* Wk = (const float*)d_in[2];
    const float* Wv = (const float*)d_in[3];
    const float* Wo = (const float*)d_in[4];
    const float* W1 = (const float*)d_in[5];
    const float* W2 = (const float*)d_in[6];
    const float* g1 = (const float*)d_in[7];
    const float* b1 = (const float*)d_in[8];
    const float* g2 = (const float*)d_in[9];
    const float* b2 = (const float*)d_in[10];
    float* out = (float*)d_out;

    __half *px, *pwq, *pwk, *pwv, *pwo, *pw1, *pw2;
    __half *pq, *pk, *pvt, *pattn, *px1h, *pff;
    float *pproj, *px1;
    cudaGetSymbolAddress((void**)&px,   hx);
    cudaGetSymbolAddress((void**)&pwq,  hWq);
    cudaGetSymbolAddress((void**)&pwk,  hWk);
    cudaGetSymbolAddress((void**)&pwv,  hWv);
    cudaGetSymbolAddress((void**)&pwo,  hWo);
    cudaGetSymbolAddress((void**)&pw1,  hW1);
    cudaGetSymbolAddress((void**)&pw2,  hW2);
    cudaGetSymbolAddress((void**)&pq,   hq);
    cudaGetSymbolAddress((void**)&pk,   hk);
    cudaGetSymbolAddress((void**)&pvt,  hvt);
    cudaGetSymbolAddress((void**)&pattn,hattn);
    cudaGetSymbolAddress((void**)&px1h, hx1);
    cudaGetSymbolAddress((void**)&pff,  hff);
    cudaGetSymbolAddress((void**)&pproj,g_proj);
    cudaGetSymbolAddress((void**)&px1,  g_x1);

    cudaFuncSetAttribute(gemm256<0>, cudaFuncAttributeMaxDynamicSharedMemorySize, GEMM2_SMEM);
    cudaFuncSetAttribute(gemm256<3>, cudaFuncAttributeMaxDynamicSharedMemorySize, GEMM2_SMEM);
    cudaFuncSetAttribute(gemm256<4>, cudaFuncAttributeMaxDynamicSharedMemorySize, GEMM2_SMEM);
    cudaFuncSetAttribute(gemm_qkv,   cudaFuncAttributeMaxDynamicSharedMemorySize, GEMM2_SMEM);
    cudaFuncSetAttribute(flash_h,    cudaFuncAttributeMaxDynamicSharedMemorySize, FLASHH_SMEM);

    dim3 blk(256);

    // fp32 -> fp16, single launch
    f2h_all<<<dim3(TOKENS * DMODEL / 1024, 7), blk>>>(
        x, px, Wq, pwq, Wk, pwk, Wv, pwv, Wo, pwo, W1, pw1, W2, pw2);

    // fused QKV projections
    gemm_qkv<<<dim3(12, TOKENS / 128), blk, GEMM2_SMEM>>>(
        px, pwq, pwk, pwv, pq, pk, pvt);

    // attention
    dim3 gattn(SEQ / 128, 2 * NHEADS);
    flash_h<<<gattn, blk, FLASHH_SMEM>>>(pq, pk, pvt, pattn);

    // output projection + residual + LN1
    gemm256<4><<<dim3(DMODEL / 256, TOKENS / 128), blk, GEMM2_SMEM>>>(
        pattn, pwo, pproj, TOKENS, DMODEL, DMODEL);
    add_ln2<<<TOKENS, 256>>>(x, pproj, g1, b1, px1, px1h);

    // FF1 (+GELU), FF2, residual + LN2
    gemm256<3><<<dim3(DFF / 256, TOKENS / 128), blk, GEMM2_SMEM>>>(
        px1h, pw1, pff, TOKENS, DFF, DMODEL);
    gemm256<4><<<dim3(DMODEL / 256, TOKENS / 128), blk, GEMM2_SMEM>>>(
        pff, pw2, pproj, TOKENS, DMODEL, DFF);
    add_ln2<<<TOKENS, 256>>>(px1, pproj, g2, b2, out, px1h);
}

// round 8
// speedup vs baseline: 7.3788x; 1.0605x over previous
#include <cuda_runtime.h>
#include <cuda_fp16.h>
#include <math.h>
#include <cstdint>

// ---------------------------------------------------------------------------
// Problem constants
// ---------------------------------------------------------------------------
#define TOKENS 4096        // B*S = 2*2048
#define DMODEL 1024
#define DFF    4096
#define NHEADS 16
#define DK     64
#define SEQ    2048

// ---------------------------------------------------------------------------
// Scratch (device globals)
// ---------------------------------------------------------------------------
__device__ __half hx   [TOKENS * DMODEL];
__device__ __half hWq  [DMODEL * DMODEL];
__device__ __half hWk  [DMODEL * DMODEL];
__device__ __half hWv  [DMODEL * DMODEL];
__device__ __half hWo  [DMODEL * DMODEL];
__device__ __half hW1  [DFF * DMODEL];
__device__ __half hW2  [DMODEL * DFF];
__device__ __half hq   [TOKENS * DMODEL];   // pre-scaled by 1/8
__device__ __half hk   [TOKENS * DMODEL];
__device__ __half hvt  [TOKENS * DMODEL];   // V transposed: [b][h][d][s]
__device__ __half hattn[TOKENS * DMODEL];
__device__ __half hx1  [TOKENS * DMODEL];
__device__ __half hff  [TOKENS * DFF];
__device__ float  g_proj[TOKENS * DMODEL];
__device__ float  g_x1 [TOKENS * DMODEL];

// ---------------------------------------------------------------------------
// Helpers
// ---------------------------------------------------------------------------
__device__ __forceinline__ uint32_t smem_u32(const void* p) {
    uint32_t a;
    asm("{ .reg .u64 t; cvta.to.shared.u64 t, %1; cvt.u32.u64 %0, t; }"
        : "=r"(a) : "l"(p));
    return a;
}

#define CP_ASYNC16(dst_u32, src_ptr) \
    asm volatile("cp.async.cg.shared.global [%0], [%1], 16;" \
        :: "r"(dst_u32), "l"(src_ptr))
#define CP_COMMIT() asm volatile("cp.async.commit_group;")
#define CP_WAIT(n)  asm volatile("cp.async.wait_group %0;" :: "n"(n))

#define MMA_F16(c, a0, a1, a2, a3, b0, b1) \
    asm volatile("mma.sync.aligned.m16n8k16.row.col.f32.f16.f16.f32 " \
        "{%0,%1,%2,%3}, {%4,%5,%6,%7}, {%8,%9}, {%0,%1,%2,%3};" \
        : "+f"((c)[0]), "+f"((c)[1]), "+f"((c)[2]), "+f"((c)[3]) \
        : "r"(a0), "r"(a1), "r"(a2), "r"(a3), "r"(b0), "r"(b1))

#define LDSM4(r, addr) \
    asm volatile("ldmatrix.sync.aligned.m8n8.x4.shared.b16 {%0,%1,%2,%3}, [%4];" \
        : "=r"((r)[0]), "=r"((r)[1]), "=r"((r)[2]), "=r"((r)[3]) : "r"(addr))

__device__ __forceinline__ uint32_t pack_h2(float lo, float hi) {
    __half2 h = __floats2half2_rn(lo, hi);
    return *reinterpret_cast<uint32_t*>(&h);
}

// ---------------------------------------------------------------------------
// fp32 -> fp16 conversion, all tensors in one launch (grid.y selects tensor)
// ---------------------------------------------------------------------------
__global__ __launch_bounds__(256)
void f2h_all(const float* x,  __half* dx,
             const float* w0, __half* d0, const float* w1, __half* d1,
             const float* w2, __half* d2, const float* w3, __half* d3,
             const float* w4, __half* d4, const float* w5, __half* d5)
{
    const float* src; __half* dst; int n;
    switch (blockIdx.y) {
        case 0: src = x;  dst = dx; n = TOKENS * DMODEL; break;
        case 1: src = w0; dst = d0; n = DMODEL * DMODEL; break;
        case 2: src = w1; dst = d1; n = DMODEL * DMODEL; break;
        case 3: src = w2; dst = d2; n = DMODEL * DMODEL; break;
        case 4: src = w3; dst = d3; n = DMODEL * DMODEL; break;
        case 5: src = w4; dst = d4; n = DFF * DMODEL;    break;
        default:src = w5; dst = d5; n = DMODEL * DFF;    break;
    }
    int i = (blockIdx.x * 256 + threadIdx.x) * 4;
    if (i < n) {
        float4 v = *(const float4*)(src + i);
        *(__half2*)(dst + i)     = __floats2half2_rn(v.x, v.y);
        *(__half2*)(dst + i + 2) = __floats2half2_rn(v.z, v.w);
    }
}

// ---------------------------------------------------------------------------
// 128(M) x 128(N) x BK=64 fp16 GEMM, 3-stage cp.async, 2 CTAs/SM.
// 256 threads, 8 warps (2m x 4n), warp tile 64x32.
// smem: 3 * (128+128) * 72 halves = 108 KB/CTA -> 216 KB/SM at occ 2.
// ---------------------------------------------------------------------------
#define HSTR   72
#define OPTILE (128 * HSTR)                      // halves, one operand stage
#define NSTAGE 3
#define GEMM_SMEM (2 * NSTAGE * OPTILE * 2)      // 110592 B

#define GEMM_IDS \
    const int tid = threadIdx.x; \
    const int wid = tid >> 5; \
    const int lid = tid & 31; \
    const int gid = lid >> 2; \
    const int tig = lid & 3; \
    const int wm0 = (wid & 1) * 64; \
    const int wn0 = (wid >> 1) * 32; \
    const int ldRow = tid >> 3; \
    const int ldC8  = (tid & 7) << 3; \
    const int a_moff = (lid & 7) + ((lid >> 3) & 1) * 8; \
    const int a_koff = (lid >> 4) * 8; \
    const int b_noff = (lid & 7) + ((lid >> 4) & 1) * 8; \
    const int b_koff = ((lid >> 3) & 1) * 8;

#define GEMM_SMEM_PTRS \
    extern __shared__ __half hsm[]; \
    uint32_t sA_u[NSTAGE], sB_u[NSTAGE]; \
    _Pragma("unroll") \
    for (int s_ = 0; s_ < NSTAGE; s_++) { \
        sA_u[s_] = smem_u32(hsm + s_ * OPTILE); \
        sB_u[s_] = smem_u32(hsm + (NSTAGE + s_) * OPTILE); \
    }

#define GEMM_LOAD_TILE(kt, buf, Ab, Bb, K) do { \
    const __half* Ak_ = (Ab) + (size_t)(kt) * 64; \
    const __half* Bk_ = (Bb) + (size_t)(kt) * 64; \
    _Pragma("unroll") \
    for (int it = 0; it < 4; it++) { \
        int row = ldRow + it * 32; \
        uint32_t so_ = (uint32_t)(row * HSTR + ldC8) * 2u; \
        CP_ASYNC16(sA_u[buf] + so_, Ak_ + (size_t)row * (K) + ldC8); \
        CP_ASYNC16(sB_u[buf] + so_, Bk_ + (size_t)row * (K) + ldC8); \
    } \
    CP_COMMIT(); \
} while (0)

#define GEMM_COMPUTE_TILE(buf, acc) do { \
    const uint32_t aB_ = sA_u[buf] + (uint32_t)((wm0 + a_moff) * HSTR + a_koff) * 2u; \
    const uint32_t bB_ = sB_u[buf] + (uint32_t)((wn0 + b_noff) * HSTR + b_koff) * 2u; \
    _Pragma("unroll") \
    for (int ks = 0; ks < 4; ks++) { \
        uint32_t a[4][4], b[2][4]; \
        _Pragma("unroll") \
        for (int fm = 0; fm < 4; fm++) \
            LDSM4(a[fm], aB_ + (uint32_t)(fm * 16 * HSTR) * 2u + ks * 32); \
        _Pragma("unroll") \
        for (int fn2 = 0; fn2 < 2; fn2++) \
            LDSM4(b[fn2], bB_ + (uint32_t)(fn2 * 16 * HSTR) * 2u + ks * 32); \
        _Pragma("unroll") \
        for (int fm = 0; fm < 4; fm++) \
            _Pragma("unroll") \
            for (int fn = 0; fn < 4; fn++) \
                MMA_F16(acc[fm][fn], \
                        a[fm][0], a[fm][1], a[fm][2], a[fm][3], \
                        b[fn >> 1][(fn & 1) * 2], b[fn >> 1][(fn & 1) * 2 + 1]); \
    } \
} while (0)

#define GEMM_MAINLOOP(Ab, Bb, K, acc) do { \
    const int KT_ = (K) >> 6; \
    GEMM_LOAD_TILE(0, 0, Ab, Bb, K); \
    GEMM_LOAD_TILE(1, 1, Ab, Bb, K); \
    for (int kt = 0; kt < KT_; kt++) { \
        const int buf = kt % NSTAGE; \
        if (kt + 2 < KT_) { \
            GEMM_LOAD_TILE(kt + 2, (kt + 2) % NSTAGE, Ab, Bb, K); \
            CP_WAIT(2); \
        } else if (kt + 1 < KT_) { CP_WAIT(1); } \
        else                     { CP_WAIT(0); } \
        __syncthreads(); \
        GEMM_COMPUTE_TILE(buf, acc); \
        __syncthreads(); \
    } \
} while (0)

// ---------------------------------------------------------------------------
// General GEMM:  C[M,N] = A[M,K] @ B[N,K]^T
// EPI: 0 = fp16, 3 = exact GELU -> fp16, 4 = fp32
// ---------------------------------------------------------------------------
template <int EPI>
__global__ __launch_bounds__(256, 2)
void gemm128(const __half* __restrict__ A, const __half* __restrict__ B,
             void* __restrict__ Cv, int M, int N, int K)
{
    GEMM_SMEM_PTRS
    GEMM_IDS
    const int bm = blockIdx.y * 128;
    const int bn = blockIdx.x * 128;

    const __half* Ab = A + (size_t)bm * K;
    const __half* Bb = B + (size_t)bn * K;

    float acc[4][4][4];
#pragma unroll
    for (int i = 0; i < 4; i++)
#pragma unroll
        for (int j = 0; j < 4; j++)
#pragma unroll
            for (int r = 0; r < 4; r++) acc[i][j][r] = 0.f;

    GEMM_MAINLOOP(Ab, Bb, K, acc);

#pragma unroll
    for (int fm = 0; fm < 4; fm++) {
#pragma unroll
        for (int fn = 0; fn < 4; fn++) {
            float v[4];
#pragma unroll
            for (int r = 0; r < 4; r++) {
                float t = acc[fm][fn][r];
                if (EPI == 3) t = 0.5f * t * (1.f + erff(t * 0.70710678118654752f));
                v[r] = t;
            }
            const int row0 = bm + wm0 + fm * 16 + gid;
            const int col  = bn + wn0 + fn * 8 + tig * 2;
            if (EPI == 4) {
                float* C = (float*)Cv;
                *(float2*)(C + (size_t)row0 * N + col)       = make_float2(v[0], v[1]);
                *(float2*)(C + (size_t)(row0 + 8) * N + col) = make_float2(v[2], v[3]);
            } else {
                __half* C = (__half*)Cv;
                *(__half2*)(C + (size_t)row0 * N + col) =
                    __floats2half2_rn(v[0], v[1]);
                *(__half2*)(C + (size_t)(row0 + 8) * N + col) =
                    __floats2half2_rn(v[2], v[3]);
            }
        }
    }
}

// ---------------------------------------------------------------------------
// Fused QKV GEMM. grid.x = 24: weight w = blockIdx.x >> 3,
// bn = (blockIdx.x & 7) * 128. Epilogue: w=0 Q*0.125, w=1 K plain, w=2 V^T.
// ---------------------------------------------------------------------------
__global__ __launch_bounds__(256, 2)
void gemm_qkv(const __half* __restrict__ A,
              const __half* __restrict__ Bq, const __half* __restrict__ Bk,
              const __half* __restrict__ Bv,
              __half* __restrict__ Cq, __half* __restrict__ Ck,
              __half* __restrict__ Cvt)
{
    GEMM_SMEM_PTRS
    GEMM_IDS
    const int K  = DMODEL;
    const int w  = blockIdx.x >> 3;
    const int bn = (blockIdx.x & 7) * 128;
    const int bm = blockIdx.y * 128;

    const __half* Bsel = (w == 0) ? Bq : (w == 1) ? Bk : Bv;
    const __half* Ab = A + (size_t)bm * K;
    const __half* Bb = Bsel + (size_t)bn * K;

    float acc[4][4][4];
#pragma unroll
    for (int i = 0; i < 4; i++)
#pragma unroll
        for (int j = 0; j < 4; j++)
#pragma unroll
            for (int r = 0; r < 4; r++) acc[i][j][r] = 0.f;

    GEMM_MAINLOOP(Ab, Bb, K, acc);

#pragma unroll
    for (int fm = 0; fm < 4; fm++) {
#pragma unroll
        for (int fn = 0; fn < 4; fn++) {
            const int row0 = bm + wm0 + fm * 16 + gid;
            const int col  = bn + wn0 + fn * 8 + tig * 2;
            float* v = acc[fm][fn];
            if (w == 0) {
                *(__half2*)(Cq + (size_t)row0 * DMODEL + col) =
                    __floats2half2_rn(v[0] * 0.125f, v[1] * 0.125f);
                *(__half2*)(Cq + (size_t)(row0 + 8) * DMODEL + col) =
                    __floats2half2_rn(v[2] * 0.125f, v[3] * 0.125f);
            } else if (w == 1) {
                *(__half2*)(Ck + (size_t)row0 * DMODEL + col) =
                    __floats2half2_rn(v[0], v[1]);
                *(__half2*)(Ck + (size_t)(row0 + 8) * DMODEL + col) =
                    __floats2half2_rn(v[2], v[3]);
            } else {
#pragma unroll
                for (int ri = 0; ri < 2; ri++) {
#pragma unroll
                    for (int ci = 0; ci < 2; ci++) {
                        int r = row0 + ri * 8;
                        int c = col + ci;
                        int bb = r >> 11, ss = r & 2047;
                        int hh = c >> 6,  dd = c & 63;
                        Cvt[(((size_t)(bb * 16 + hh)) * 64 + dd) * SEQ + ss] =
                            __float2half(v[ri * 2 + ci]);
                    }
                }
            }
        }
    }
}

// ---------------------------------------------------------------------------
// Flash attention: fp16 mma + ldmatrix, Q frags in regs, 2 CTAs/SM.
// ---------------------------------------------------------------------------
#define FQS 72
#define FLASHH_SMEM ((128 * FQS + 4 * 64 * FQS) * 2)   // 55296 B

__global__ __launch_bounds__(256, 2)
void flash_h(const __half* __restrict__ Q, const __half* __restrict__ K,
             const __half* __restrict__ Vt, __half* __restrict__ Oa)
{
    extern __shared__ __half fsh[];
    __half* Qs = fsh;
    const uint32_t qs_u = smem_u32(Qs);
    const uint32_t ks_u[2] = { smem_u32(Qs + 128 * FQS),
                               smem_u32(Qs + 128 * FQS + 64 * FQS) };
    const uint32_t vs_u[2] = { smem_u32(Qs + 128 * FQS + 2 * 64 * FQS),
                               smem_u32(Qs + 128 * FQS + 3 * 64 * FQS) };

    const int tid = threadIdx.x;
    const int wid = tid >> 5;
    const int lid = tid & 31;
    const int gid = lid >> 2;
    const int tig = lid & 3;
    const int q0  = blockIdx.x * 128;
    const int bh  = blockIdx.y;
    const int b   = bh >> 4;
    const int h   = bh & 15;
    const int m0  = wid * 16;

    const int a_moff = (lid & 7) + ((lid >> 3) & 1) * 8;
    const int a_koff = (lid >> 4) * 8;
    const int b_noff = (lid & 7) + ((lid >> 4) & 1) * 8;
    const int b_koff = ((lid >> 3) & 1) * 8;

    const size_t base = (size_t)b * SEQ * DMODEL + h * DK;
    const __half* Qb = Q + base;
    const __half* Kb = K + base;
    const __half* Vb = Vt + ((size_t)(b * 16 + h)) * 64 * SEQ;
    __half*       Ob = Oa + base;

#pragma unroll
    for (int it = 0; it < 4; it++) {
        int s   = tid + it * 256;
        int row = s >> 3;
        int c8  = (s & 7) << 3;
        CP_ASYNC16(qs_u + (uint32_t)(row * FQS + c8) * 2u,
                   Qb + (size_t)(q0 + row) * DMODEL + c8);
    }
    CP_COMMIT();

    auto load_kv = [&](int kt, int buf) {
        const __half* Kt  = Kb + (size_t)kt * 64 * DMODEL;
        const __half* Vtt = Vb + kt * 64;
#pragma unroll
        for (int it = 0; it < 2; it++) {
            int s   = tid + it * 256;
            int row = s >> 3;
            int c8  = (s & 7) << 3;
            CP_ASYNC16(ks_u[buf] + (uint32_t)(row * FQS + c8) * 2u,
                       Kt + (size_t)row * DMODEL + c8);
            CP_ASYNC16(vs_u[buf] + (uint32_t)(row * FQS + c8) * 2u,
                       Vtt + (size_t)row * SEQ + c8);
        }
        CP_COMMIT();
    };

    load_kv(0, 0);

    CP_WAIT(1);
    __syncthreads();
    uint32_t qf[4][4];
    {
        const uint32_t qB = qs_u + (uint32_t)((m0 + a_moff) * FQS + a_koff) * 2u;
#pragma unroll
        for (int kf = 0; kf < 4; kf++)
            LDSM4(qf[kf], qB + kf * 32);
    }

    float m[2] = { -1e30f, -1e30f };
    float l[2] = { 0.f, 0.f };
    float o[8][4];
#pragma unroll
    for (int d = 0; d < 8; d++)
#pragma unroll
        for (int r = 0; r < 4; r++) o[d][r] = 0.f;

    const int NT = SEQ / 64;

    for (int kt = 0; kt < NT; kt++) {
        const int buf = kt & 1;
        if (kt + 1 < NT) { load_kv(kt + 1, buf ^ 1); CP_WAIT(1); }
        else             { CP_WAIT(0); }
        __syncthreads();

        const uint32_t kB = ks_u[buf] + (uint32_t)(b_noff * FQS + b_koff) * 2u;
        const uint32_t vB = vs_u[buf] + (uint32_t)(b_noff * FQS + b_koff) * 2u;

        float s[8][4];
#pragma unroll
        for (int nf = 0; nf < 8; nf++)
#pragma unroll
            for (int r = 0; r < 4; r++) s[nf][r] = 0.f;

#pragma unroll
        for (int kf = 0; kf < 4; kf++) {
#pragma unroll
            for (int fn2 = 0; fn2 < 4; fn2++) {
                uint32_t kb[4];
                LDSM4(kb, kB + (uint32_t)(fn2 * 16 * FQS) * 2u + kf * 32);
                MMA_F16(s[2 * fn2],     qf[kf][0], qf[kf][1], qf[kf][2], qf[kf][3],
                        kb[0], kb[1]);
                MMA_F16(s[2 * fn2 + 1], qf[kf][0], qf[kf][1], qf[kf][2], qf[kf][3],
                        kb[2], kb[3]);
            }
        }

        float mx0 = -1e30f, mx1 = -1e30f;
#pragma unroll
        for (int nf = 0; nf < 8; nf++) {
            mx0 = fmaxf(mx0, fmaxf(s[nf][0], s[nf][1]));
            mx1 = fmaxf(mx1, fmaxf(s[nf][2], s[nf][3]));
        }
        mx0 = fmaxf(mx0, __shfl_xor_sync(0xffffffffu, mx0, 1));
        mx0 = fmaxf(mx0, __shfl_xor_sync(0xffffffffu, mx0, 2));
        mx1 = fmaxf(mx1, __shfl_xor_sync(0xffffffffu, mx1, 1));
        mx1 = fmaxf(mx1, __shfl_xor_sync(0xffffffffu, mx1, 2));

        const float mn0 = fmaxf(m[0], mx0);
        const float mn1 = fmaxf(m[1], mx1);
        const float al0 = __expf(m[0] - mn0);
        const float al1 = __expf(m[1] - mn1);

        float sum0 = 0.f, sum1 = 0.f;
#pragma unroll
        for (int nf = 0; nf < 8; nf++) {
            s[nf][0] = __expf(s[nf][0] - mn0);
            s[nf][1] = __expf(s[nf][1] - mn0);
            s[nf][2] = __expf(s[nf][2] - mn1);
            s[nf][3] = __expf(s[nf][3] - mn1);
            sum0 += s[nf][0] + s[nf][1];
            sum1 += s[nf][2] + s[nf][3];
        }
        sum0 += __shfl_xor_sync(0xffffffffu, sum0, 1);
        sum0 += __shfl_xor_sync(0xffffffffu, sum0, 2);
        sum1 += __shfl_xor_sync(0xffffffffu, sum1, 1);
        sum1 += __shfl_xor_sync(0xffffffffu, sum1, 2);

        l[0] = l[0] * al0 + sum0;
        l[1] = l[1] * al1 + sum1;
        m[0] = mn0;
        m[1] = mn1;

#pragma unroll
        for (int d = 0; d < 8; d++) {
            o[d][0] *= al0; o[d][1] *= al0;
            o[d][2] *= al1; o[d][3] *= al1;
        }

#pragma unroll
        for (int c = 0; c < 4; c++) {
            uint32_t a0 = pack_h2(s[2*c][0],   s[2*c][1]);
            uint32_t a1 = pack_h2(s[2*c][2],   s[2*c][3]);
            uint32_t a2 = pack_h2(s[2*c+1][0], s[2*c+1][1]);
            uint32_t a3 = pack_h2(s[2*c+1][2], s[2*c+1][3]);
#pragma unroll
            for (int fn2 = 0; fn2 < 4; fn2++) {
                uint32_t vb[4];
                LDSM4(vb, vB + (uint32_t)(fn2 * 16 * FQS) * 2u + c * 32);
                MMA_F16(o[2 * fn2],     a0, a1, a2, a3, vb[0], vb[1]);
                MMA_F16(o[2 * fn2 + 1], a0, a1, a2, a3, vb[2], vb[3]);
            }
        }
        __syncthreads();
    }

    const float inv0 = 1.f / l[0];
    const float inv1 = 1.f / l[1];
    const int row0 = q0 + m0 + gid;
#pragma unroll
    for (int d = 0; d < 8; d++) {
        const int col = d * 8 + tig * 2;
        *(__half2*)(Ob + (size_t)row0 * DMODEL + col) =
            __floats2half2_rn(o[d][0] * inv0, o[d][1] * inv0);
        *(__half2*)(Ob + (size_t)(row0 + 8) * DMODEL + col) =
            __floats2half2_rn(o[d][2] * inv1, o[d][3] * inv1);
    }
}

// ---------------------------------------------------------------------------
// y = LayerNorm(a + b) * gamma + beta; dual output (fp32 + fp16)
// ---------------------------------------------------------------------------
__global__ __launch_bounds__(256)
void add_ln2(const float* __restrict__ a, const float* __restrict__ b,
             const float* __restrict__ gamma, const float* __restrict__ beta,
             float* __restrict__ y, __half* __restrict__ yh)
{
    const int row = blockIdx.x;
    const int tid = threadIdx.x;
    __shared__ float rs[256], rq[256];

    float4 va = ((const float4*)(a + (size_t)row * DMODEL))[tid];
    float4 vb = ((const float4*)(b + (size_t)row * DMODEL))[tid];
    float s0 = va.x + vb.x, s1 = va.y + vb.y, s2 = va.z + vb.z, s3 = va.w + vb.w;

    rs[tid] = s0 + s1 + s2 + s3;
    rq[tid] = s0 * s0 + s1 * s1 + s2 * s2 + s3 * s3;
    __syncthreads();
#pragma unroll
    for (int off = 128; off > 0; off >>= 1) {
        if (tid < off) { rs[tid] += rs[tid + off]; rq[tid] += rq[tid + off]; }
        __syncthreads();
    }
    const float mu   = rs[0] * (1.f / DMODEL);
    const float var  = rq[0] * (1.f / DMODEL) - mu * mu;
    const float rinv = rsqrtf(var + 1e-5f);

    float4 g  = ((const float4*)gamma)[tid];
    float4 be = ((const float4*)beta)[tid];
    float4 out;
    out.x = (s0 - mu) * rinv * g.x + be.x;
    out.y = (s1 - mu) * rinv * g.y + be.y;
    out.z = (s2 - mu) * rinv * g.z + be.z;
    out.w = (s3 - mu) * rinv * g.w + be.w;
    ((float4*)(y + (size_t)row * DMODEL))[tid] = out;

    __half* hp = yh + (size_t)row * DMODEL + tid * 4;
    *(__half2*)(hp)     = __floats2half2_rn(out.x, out.y);
    *(__half2*)(hp + 2) = __floats2half2_rn(out.z, out.w);
}

// ---------------------------------------------------------------------------
// launch
// ---------------------------------------------------------------------------
extern "C" void kernel_launch(void* const* d_in, const int* in_sizes, int n_in,
                              void* d_out, int out_size)
{
    const float* x  = (const float*)d_in[0];
    const float* Wq = (const float*)d_in[1];
    const float* Wk = (const float*)d_in[2];
    const float* Wv = (const float*)d_in[3];
    const float* Wo = (const float*)d_in[4];
    const float* W1 = (const float*)d_in[5];
    const float* W2 = (const float*)d_in[6];
    const float* g1 = (const float*)d_in[7];
    const float* b1 = (const float*)d_in[8];
    const float* g2 = (const float*)d_in[9];
    const float* b2 = (const float*)d_in[10];
    float* out = (float*)d_out;

    __half *px, *pwq, *pwk, *pwv, *pwo, *pw1, *pw2;
    __half *pq, *pk, *pvt, *pattn, *px1h, *pff;
    float *pproj, *px1;
    cudaGetSymbolAddress((void**)&px,   hx);
    cudaGetSymbolAddress((void**)&pwq,  hWq);
    cudaGetSymbolAddress((void**)&pwk,  hWk);
    cudaGetSymbolAddress((void**)&pwv,  hWv);
    cudaGetSymbolAddress((void**)&pwo,  hWo);
    cudaGetSymbolAddress((void**)&pw1,  hW1);
    cudaGetSymbolAddress((void**)&pw2,  hW2);
    cudaGetSymbolAddress((void**)&pq,   hq);
    cudaGetSymbolAddress((void**)&pk,   hk);
    cudaGetSymbolAddress((void**)&pvt,  hvt);
    cudaGetSymbolAddress((void**)&pattn,hattn);
    cudaGetSymbolAddress((void**)&px1h, hx1);
    cudaGetSymbolAddress((void**)&pff,  hff);
    cudaGetSymbolAddress((void**)&pproj,g_proj);
    cudaGetSymbolAddress((void**)&px1,  g_x1);

    cudaFuncSetAttribute(gemm128<0>, cudaFuncAttributeMaxDynamicSharedMemorySize, GEMM_SMEM);
    cudaFuncSetAttribute(gemm128<3>, cudaFuncAttributeMaxDynamicSharedMemorySize, GEMM_SMEM);
    cudaFuncSetAttribute(gemm128<4>, cudaFuncAttributeMaxDynamicSharedMemorySize, GEMM_SMEM);
    cudaFuncSetAttribute(gemm_qkv,   cudaFuncAttributeMaxDynamicSharedMemorySize, GEMM_SMEM);
    cudaFuncSetAttribute(flash_h,    cudaFuncAttributeMaxDynamicSharedMemorySize, FLASHH_SMEM);

    dim3 blk(256);

    // fp32 -> fp16, single launch
    f2h_all<<<dim3(TOKENS * DMODEL / 1024, 7), blk>>>(
        x, px, Wq, pwq, Wk, pwk, Wv, pwv, Wo, pwo, W1, pw1, W2, pw2);

    // fused QKV projections (grid.x = 3 weights * 8 n-tiles)
    gemm_qkv<<<dim3(24, TOKENS / 128), blk, GEMM_SMEM>>>(
        px, pwq, pwk, pwv, pq, pk, pvt);

    // attention
    dim3 gattn(SEQ / 128, 2 * NHEADS);
    flash_h<<<gattn, blk, FLASHH_SMEM>>>(pq, pk, pvt, pattn);

    // output projection + residual + LN1
    gemm128<4><<<dim3(DMODEL / 128, TOKENS / 128), blk, GEMM_SMEM>>>(
        pattn, pwo, pproj, TOKENS, DMODEL, DMODEL);
    add_ln2<<<TOKENS, 256>>>(x, pproj, g1, b1, px1, px1h);

    // FF1 (+GELU), FF2, residual + LN2
    gemm128<3><<<dim3(DFF / 128, TOKENS / 128), blk, GEMM_SMEM>>>(
        px1h, pw1, pff, TOKENS, DFF, DMODEL);
    gemm128<4><<<dim3(DMODEL / 128, TOKENS / 128), blk, GEMM_SMEM>>>(
        pff, pw2, pproj, TOKENS, DMODEL, DFF);
    add_ln2<<<TOKENS, 256>>>(px1, pproj, g2, b2, out, px1h);
}

// round 9
// speedup vs baseline: 8.0837x; 1.0955x over previous
#include <cuda_runtime.h>
#include <cuda_fp16.h>
#include <math.h>
#include <cstdint>

// ---------------------------------------------------------------------------
// Problem constants
// ---------------------------------------------------------------------------
#define TOKENS 4096        // B*S = 2*2048
#define DMODEL 1024
#define DFF    4096
#define NHEADS 16
#define DK     64
#define SEQ    2048

// ---------------------------------------------------------------------------
// Scratch (device globals)
// ---------------------------------------------------------------------------
__device__ __half hx   [TOKENS * DMODEL];
__device__ __half hWq  [DMODEL * DMODEL];
__device__ __half hWk  [DMODEL * DMODEL];
__device__ __half hWv  [DMODEL * DMODEL];
__device__ __half hWo  [DMODEL * DMODEL];
__device__ __half hW1  [DFF * DMODEL];
__device__ __half hW2  [DMODEL * DFF];
__device__ __half hq   [TOKENS * DMODEL];   // pre-scaled by 1/8
__device__ __half hk   [TOKENS * DMODEL];
__device__ __half hvt  [TOKENS * DMODEL];   // V transposed: [b][h][d][s]
__device__ __half hattn[TOKENS * DMODEL];
__device__ __half hx1  [TOKENS * DMODEL];
__device__ __half hff  [TOKENS * DFF];
__device__ float  g_proj[TOKENS * DMODEL];
__device__ float  g_x1 [TOKENS * DMODEL];

// ---------------------------------------------------------------------------
// Helpers
// ---------------------------------------------------------------------------
__device__ __forceinline__ uint32_t smem_u32(const void* p) {
    uint32_t a;
    asm("{ .reg .u64 t; cvta.to.shared.u64 t, %1; cvt.u32.u64 %0, t; }"
        : "=r"(a) : "l"(p));
    return a;
}

#define CP_ASYNC16(dst_u32, src_ptr) \
    asm volatile("cp.async.cg.shared.global [%0], [%1], 16;" \
        :: "r"(dst_u32), "l"(src_ptr))
#define CP_COMMIT() asm volatile("cp.async.commit_group;")
#define CP_WAIT(n)  asm volatile("cp.async.wait_group %0;" :: "n"(n))

#define MMA_F16(c, a0, a1, a2, a3, b0, b1) \
    asm volatile("mma.sync.aligned.m16n8k16.row.col.f32.f16.f16.f32 " \
        "{%0,%1,%2,%3}, {%4,%5,%6,%7}, {%8,%9}, {%0,%1,%2,%3};" \
        : "+f"((c)[0]), "+f"((c)[1]), "+f"((c)[2]), "+f"((c)[3]) \
        : "r"(a0), "r"(a1), "r"(a2), "r"(a3), "r"(b0), "r"(b1))

#define LDSM4(r, addr) \
    asm volatile("ldmatrix.sync.aligned.m8n8.x4.shared.b16 {%0,%1,%2,%3}, [%4];" \
        : "=r"((r)[0]), "=r"((r)[1]), "=r"((r)[2]), "=r"((r)[3]) : "r"(addr))

__device__ __forceinline__ uint32_t pack_h2(float lo, float hi) {
    __half2 h = __floats2half2_rn(lo, hi);
    return *reinterpret_cast<uint32_t*>(&h);
}

// ---------------------------------------------------------------------------
// fp32 -> fp16 conversion, all tensors in one launch (grid.y selects tensor)
// ---------------------------------------------------------------------------
__global__ __launch_bounds__(256)
void f2h_all(const float* x,  __half* dx,
             const float* w0, __half* d0, const float* w1, __half* d1,
             const float* w2, __half* d2, const float* w3, __half* d3,
             const float* w4, __half* d4, const float* w5, __half* d5)
{
    const float* src; __half* dst; int n;
    switch (blockIdx.y) {
        case 0: src = x;  dst = dx; n = TOKENS * DMODEL; break;
        case 1: src = w0; dst = d0; n = DMODEL * DMODEL; break;
        case 2: src = w1; dst = d1; n = DMODEL * DMODEL; break;
        case 3: src = w2; dst = d2; n = DMODEL * DMODEL; break;
        case 4: src = w3; dst = d3; n = DMODEL * DMODEL; break;
        case 5: src = w4; dst = d4; n = DFF * DMODEL;    break;
        default:src = w5; dst = d5; n = DMODEL * DFF;    break;
    }
    int i = (blockIdx.x * 256 + threadIdx.x) * 4;
    if (i < n) {
        float4 v = *(const float4*)(src + i);
        *(__half2*)(dst + i)     = __floats2half2_rn(v.x, v.y);
        *(__half2*)(dst + i + 2) = __floats2half2_rn(v.z, v.w);
    }
}

// ---------------------------------------------------------------------------
// 128(M) x 128(N) x BK=64 fp16 GEMM, 3-stage cp.async, 2 CTAs/SM,
// single-barrier multistage mainloop (CUTLASS form).
// ---------------------------------------------------------------------------
#define HSTR   72
#define OPTILE (128 * HSTR)
#define NSTAGE 3
#define GEMM_SMEM (2 * NSTAGE * OPTILE * 2)      // 110592 B

#define GEMM_IDS \
    const int tid = threadIdx.x; \
    const int wid = tid >> 5; \
    const int lid = tid & 31; \
    const int gid = lid >> 2; \
    const int tig = lid & 3; \
    const int wm0 = (wid & 1) * 64; \
    const int wn0 = (wid >> 1) * 32; \
    const int ldRow = tid >> 3; \
    const int ldC8  = (tid & 7) << 3; \
    const int a_moff = (lid & 7) + ((lid >> 3) & 1) * 8; \
    const int a_koff = (lid >> 4) * 8; \
    const int b_noff = (lid & 7) + ((lid >> 4) & 1) * 8; \
    const int b_koff = ((lid >> 3) & 1) * 8;

#define GEMM_SMEM_PTRS \
    extern __shared__ __half hsm[]; \
    uint32_t sA_u[NSTAGE], sB_u[NSTAGE]; \
    _Pragma("unroll") \
    for (int s_ = 0; s_ < NSTAGE; s_++) { \
        sA_u[s_] = smem_u32(hsm + s_ * OPTILE); \
        sB_u[s_] = smem_u32(hsm + (NSTAGE + s_) * OPTILE); \
    }

#define GEMM_LOAD_TILE(kt, buf, Ab, Bb, K) do { \
    const __half* Ak_ = (Ab) + (size_t)(kt) * 64; \
    const __half* Bk_ = (Bb) + (size_t)(kt) * 64; \
    _Pragma("unroll") \
    for (int it = 0; it < 4; it++) { \
        int row = ldRow + it * 32; \
        uint32_t so_ = (uint32_t)(row * HSTR + ldC8) * 2u; \
        CP_ASYNC16(sA_u[buf] + so_, Ak_ + (size_t)row * (K) + ldC8); \
        CP_ASYNC16(sB_u[buf] + so_, Bk_ + (size_t)row * (K) + ldC8); \
    } \
    CP_COMMIT(); \
} while (0)

#define GEMM_COMPUTE_TILE(buf, acc) do { \
    const uint32_t aB_ = sA_u[buf] + (uint32_t)((wm0 + a_moff) * HSTR + a_koff) * 2u; \
    const uint32_t bB_ = sB_u[buf] + (uint32_t)((wn0 + b_noff) * HSTR + b_koff) * 2u; \
    _Pragma("unroll") \
    for (int ks = 0; ks < 4; ks++) { \
        uint32_t a[4][4], b[2][4]; \
        _Pragma("unroll") \
        for (int fm = 0; fm < 4; fm++) \
            LDSM4(a[fm], aB_ + (uint32_t)(fm * 16 * HSTR) * 2u + ks * 32); \
        _Pragma("unroll") \
        for (int fn2 = 0; fn2 < 2; fn2++) \
            LDSM4(b[fn2], bB_ + (uint32_t)(fn2 * 16 * HSTR) * 2u + ks * 32); \
        _Pragma("unroll") \
        for (int fm = 0; fm < 4; fm++) \
            _Pragma("unroll") \
            for (int fn = 0; fn < 4; fn++) \
                MMA_F16(acc[fm][fn], \
                        a[fm][0], a[fm][1], a[fm][2], a[fm][3], \
                        b[fn >> 1][(fn & 1) * 2], b[fn >> 1][(fn & 1) * 2 + 1]); \
    } \
} while (0)

// Single-barrier multistage: wait(kt) -> barrier -> compute(kt) -> load(kt+2).
// load target stage (kt+2)%3 == (kt-1)%3 was last read in iter kt-1; the
// barrier at top of iter kt guarantees all warps finished that compute.
#define GEMM_MAINLOOP(Ab, Bb, K, acc) do { \
    const int KT_ = (K) >> 6; \
    GEMM_LOAD_TILE(0, 0, Ab, Bb, K); \
    GEMM_LOAD_TILE(1, 1, Ab, Bb, K); \
    for (int kt = 0; kt < KT_; kt++) { \
        if (kt + 1 < KT_) { CP_WAIT(1); } else { CP_WAIT(0); } \
        __syncthreads(); \
        GEMM_COMPUTE_TILE(kt % NSTAGE, acc); \
        if (kt + 2 < KT_) GEMM_LOAD_TILE(kt + 2, (kt + 2) % NSTAGE, Ab, Bb, K); \
    } \
} while (0)

// ---------------------------------------------------------------------------
// General GEMM:  C[M,N] = A[M,K] @ B[N,K]^T
// EPI: 0 = fp16, 3 = exact GELU -> fp16, 4 = fp32
// ---------------------------------------------------------------------------
template <int EPI>
__global__ __launch_bounds__(256, 2)
void gemm128(const __half* __restrict__ A, const __half* __restrict__ B,
             void* __restrict__ Cv, int M, int N, int K)
{
    GEMM_SMEM_PTRS
    GEMM_IDS
    const int bm = blockIdx.y * 128;
    const int bn = blockIdx.x * 128;

    const __half* Ab = A + (size_t)bm * K;
    const __half* Bb = B + (size_t)bn * K;

    float acc[4][4][4];
#pragma unroll
    for (int i = 0; i < 4; i++)
#pragma unroll
        for (int j = 0; j < 4; j++)
#pragma unroll
            for (int r = 0; r < 4; r++) acc[i][j][r] = 0.f;

    GEMM_MAINLOOP(Ab, Bb, K, acc);

#pragma unroll
    for (int fm = 0; fm < 4; fm++) {
#pragma unroll
        for (int fn = 0; fn < 4; fn++) {
            float v[4];
#pragma unroll
            for (int r = 0; r < 4; r++) {
                float t = acc[fm][fn][r];
                if (EPI == 3) t = 0.5f * t * (1.f + erff(t * 0.70710678118654752f));
                v[r] = t;
            }
            const int row0 = bm + wm0 + fm * 16 + gid;
            const int col  = bn + wn0 + fn * 8 + tig * 2;
            if (EPI == 4) {
                float* C = (float*)Cv;
                *(float2*)(C + (size_t)row0 * N + col)       = make_float2(v[0], v[1]);
                *(float2*)(C + (size_t)(row0 + 8) * N + col) = make_float2(v[2], v[3]);
            } else {
                __half* C = (__half*)Cv;
                *(__half2*)(C + (size_t)row0 * N + col) =
                    __floats2half2_rn(v[0], v[1]);
                *(__half2*)(C + (size_t)(row0 + 8) * N + col) =
                    __floats2half2_rn(v[2], v[3]);
            }
        }
    }
}

// ---------------------------------------------------------------------------
// Fused QKV GEMM. grid.x = 24: weight w = blockIdx.x >> 3,
// bn = (blockIdx.x & 7) * 128. Epilogue: w=0 Q*0.125, w=1 K plain, w=2 V^T.
// ---------------------------------------------------------------------------
__global__ __launch_bounds__(256, 2)
void gemm_qkv(const __half* __restrict__ A,
              const __half* __restrict__ Bq, const __half* __restrict__ Bk,
              const __half* __restrict__ Bv,
              __half* __restrict__ Cq, __half* __restrict__ Ck,
              __half* __restrict__ Cvt)
{
    GEMM_SMEM_PTRS
    GEMM_IDS
    const int K  = DMODEL;
    const int w  = blockIdx.x >> 3;
    const int bn = (blockIdx.x & 7) * 128;
    const int bm = blockIdx.y * 128;

    const __half* Bsel = (w == 0) ? Bq : (w == 1) ? Bk : Bv;
    const __half* Ab = A + (size_t)bm * K;
    const __half* Bb = Bsel + (size_t)bn * K;

    float acc[4][4][4];
#pragma unroll
    for (int i = 0; i < 4; i++)
#pragma unroll
        for (int j = 0; j < 4; j++)
#pragma unroll
            for (int r = 0; r < 4; r++) acc[i][j][r] = 0.f;

    GEMM_MAINLOOP(Ab, Bb, K, acc);

#pragma unroll
    for (int fm = 0; fm < 4; fm++) {
#pragma unroll
        for (int fn = 0; fn < 4; fn++) {
            const int row0 = bm + wm0 + fm * 16 + gid;
            const int col  = bn + wn0 + fn * 8 + tig * 2;
            float* v = acc[fm][fn];
            if (w == 0) {
                *(__half2*)(Cq + (size_t)row0 * DMODEL + col) =
                    __floats2half2_rn(v[0] * 0.125f, v[1] * 0.125f);
                *(__half2*)(Cq + (size_t)(row0 + 8) * DMODEL + col) =
                    __floats2half2_rn(v[2] * 0.125f, v[3] * 0.125f);
            } else if (w == 1) {
                *(__half2*)(Ck + (size_t)row0 * DMODEL + col) =
                    __floats2half2_rn(v[0], v[1]);
                *(__half2*)(Ck + (size_t)(row0 + 8) * DMODEL + col) =
                    __floats2half2_rn(v[2], v[3]);
            } else {
#pragma unroll
                for (int ri = 0; ri < 2; ri++) {
#pragma unroll
                    for (int ci = 0; ci < 2; ci++) {
                        int r = row0 + ri * 8;
                        int c = col + ci;
                        int bb = r >> 11, ss = r & 2047;
                        int hh = c >> 6,  dd = c & 63;
                        Cvt[(((size_t)(bb * 16 + hh)) * 64 + dd) * SEQ + ss] =
                            __float2half(v[ri * 2 + ci]);
                    }
                }
            }
        }
    }
}

// ---------------------------------------------------------------------------
// Flash attention: fp16 mma + ldmatrix, Q frags in regs, 3-stage KV,
// single barrier per KV tile, 2 CTAs/SM.
// ---------------------------------------------------------------------------
#define FQS 72
#define KVSTG 3
#define FLASHH_SMEM ((128 * FQS + 2 * KVSTG * 64 * FQS) * 2)   // 73728 B

__global__ __launch_bounds__(256, 2)
void flash_h(const __half* __restrict__ Q, const __half* __restrict__ K,
             const __half* __restrict__ Vt, __half* __restrict__ Oa)
{
    extern __shared__ __half fsh[];
    __half* Qs = fsh;
    const uint32_t qs_u = smem_u32(Qs);
    uint32_t ks_u[KVSTG], vs_u[KVSTG];
#pragma unroll
    for (int s_ = 0; s_ < KVSTG; s_++) {
        ks_u[s_] = smem_u32(Qs + 128 * FQS + s_ * 64 * FQS);
        vs_u[s_] = smem_u32(Qs + 128 * FQS + (KVSTG + s_) * 64 * FQS);
    }

    const int tid = threadIdx.x;
    const int wid = tid >> 5;
    const int lid = tid & 31;
    const int gid = lid >> 2;
    const int tig = lid & 3;
    const int q0  = blockIdx.x * 128;
    const int bh  = blockIdx.y;
    const int b   = bh >> 4;
    const int h   = bh & 15;
    const int m0  = wid * 16;

    const int a_moff = (lid & 7) + ((lid >> 3) & 1) * 8;
    const int a_koff = (lid >> 4) * 8;
    const int b_noff = (lid & 7) + ((lid >> 4) & 1) * 8;
    const int b_koff = ((lid >> 3) & 1) * 8;

    const size_t base = (size_t)b * SEQ * DMODEL + h * DK;
    const __half* Qb = Q + base;
    const __half* Kb = K + base;
    const __half* Vb = Vt + ((size_t)(b * 16 + h)) * 64 * SEQ;
    __half*       Ob = Oa + base;

    // Q tile (group 0)
#pragma unroll
    for (int it = 0; it < 4; it++) {
        int s   = tid + it * 256;
        int row = s >> 3;
        int c8  = (s & 7) << 3;
        CP_ASYNC16(qs_u + (uint32_t)(row * FQS + c8) * 2u,
                   Qb + (size_t)(q0 + row) * DMODEL + c8);
    }
    CP_COMMIT();

    auto load_kv = [&](int kt, int buf) {
        const __half* Kt  = Kb + (size_t)kt * 64 * DMODEL;
        const __half* Vtt = Vb + kt * 64;
#pragma unroll
        for (int it = 0; it < 2; it++) {
            int s   = tid + it * 256;
            int row = s >> 3;
            int c8  = (s & 7) << 3;
            CP_ASYNC16(ks_u[buf] + (uint32_t)(row * FQS + c8) * 2u,
                       Kt + (size_t)row * DMODEL + c8);
            CP_ASYNC16(vs_u[buf] + (uint32_t)(row * FQS + c8) * 2u,
                       Vtt + (size_t)row * SEQ + c8);
        }
        CP_COMMIT();
    };

    load_kv(0, 0);      // group 1
    load_kv(1, 1);      // group 2

    // hoist Q fragments (wait: Q group done; kv0/kv1 may pend)
    CP_WAIT(2);
    __syncthreads();
    uint32_t qf[4][4];
    {
        const uint32_t qB = qs_u + (uint32_t)((m0 + a_moff) * FQS + a_koff) * 2u;
#pragma unroll
        for (int kf = 0; kf < 4; kf++)
            LDSM4(qf[kf], qB + kf * 32);
    }

    float m[2] = { -1e30f, -1e30f };
    float l[2] = { 0.f, 0.f };
    float o[8][4];
#pragma unroll
    for (int d = 0; d < 8; d++)
#pragma unroll
        for (int r = 0; r < 4; r++) o[d][r] = 0.f;

    const int NT = SEQ / 64;

    for (int kt = 0; kt < NT; kt++) {
        const int buf = kt % KVSTG;
        if (kt + 1 < NT) { CP_WAIT(1); } else { CP_WAIT(0); }
        __syncthreads();

        const uint32_t kB = ks_u[buf] + (uint32_t)(b_noff * FQS + b_koff) * 2u;
        const uint32_t vB = vs_u[buf] + (uint32_t)(b_noff * FQS + b_koff) * 2u;

        // ---- S = Q @ K^T ----
        float s[8][4];
#pragma unroll
        for (int nf = 0; nf < 8; nf++)
#pragma unroll
            for (int r = 0; r < 4; r++) s[nf][r] = 0.f;

#pragma unroll
        for (int kf = 0; kf < 4; kf++) {
#pragma unroll
            for (int fn2 = 0; fn2 < 4; fn2++) {
                uint32_t kb[4];
                LDSM4(kb, kB + (uint32_t)(fn2 * 16 * FQS) * 2u + kf * 32);
                MMA_F16(s[2 * fn2],     qf[kf][0], qf[kf][1], qf[kf][2], qf[kf][3],
                        kb[0], kb[1]);
                MMA_F16(s[2 * fn2 + 1], qf[kf][0], qf[kf][1], qf[kf][2], qf[kf][3],
                        kb[2], kb[3]);
            }
        }

        // ---- online softmax ----
        float mx0 = -1e30f, mx1 = -1e30f;
#pragma unroll
        for (int nf = 0; nf < 8; nf++) {
            mx0 = fmaxf(mx0, fmaxf(s[nf][0], s[nf][1]));
            mx1 = fmaxf(mx1, fmaxf(s[nf][2], s[nf][3]));
        }
        mx0 = fmaxf(mx0, __shfl_xor_sync(0xffffffffu, mx0, 1));
        mx0 = fmaxf(mx0, __shfl_xor_sync(0xffffffffu, mx0, 2));
        mx1 = fmaxf(mx1, __shfl_xor_sync(0xffffffffu, mx1, 1));
        mx1 = fmaxf(mx1, __shfl_xor_sync(0xffffffffu, mx1, 2));

        const float mn0 = fmaxf(m[0], mx0);
        const float mn1 = fmaxf(m[1], mx1);
        const float al0 = __expf(m[0] - mn0);
        const float al1 = __expf(m[1] - mn1);

        float sum0 = 0.f, sum1 = 0.f;
#pragma unroll
        for (int nf = 0; nf < 8; nf++) {
            s[nf][0] = __expf(s[nf][0] - mn0);
            s[nf][1] = __expf(s[nf][1] - mn0);
            s[nf][2] = __expf(s[nf][2] - mn1);
            s[nf][3] = __expf(s[nf][3] - mn1);
            sum0 += s[nf][0] + s[nf][1];
            sum1 += s[nf][2] + s[nf][3];
        }
        sum0 += __shfl_xor_sync(0xffffffffu, sum0, 1);
        sum0 += __shfl_xor_sync(0xffffffffu, sum0, 2);
        sum1 += __shfl_xor_sync(0xffffffffu, sum1, 1);
        sum1 += __shfl_xor_sync(0xffffffffu, sum1, 2);

        l[0] = l[0] * al0 + sum0;
        l[1] = l[1] * al1 + sum1;
        m[0] = mn0;
        m[1] = mn1;

#pragma unroll
        for (int d = 0; d < 8; d++) {
            o[d][0] *= al0; o[d][1] *= al0;
            o[d][2] *= al1; o[d][3] *= al1;
        }

        // ---- O += P @ V ----
#pragma unroll
        for (int c = 0; c < 4; c++) {
            uint32_t a0 = pack_h2(s[2*c][0],   s[2*c][1]);
            uint32_t a1 = pack_h2(s[2*c][2],   s[2*c][3]);
            uint32_t a2 = pack_h2(s[2*c+1][0], s[2*c+1][1]);
            uint32_t a3 = pack_h2(s[2*c+1][2], s[2*c+1][3]);
#pragma unroll
            for (int fn2 = 0; fn2 < 4; fn2++) {
                uint32_t vb[4];
                LDSM4(vb, vB + (uint32_t)(fn2 * 16 * FQS) * 2u + c * 32);
                MMA_F16(o[2 * fn2],     a0, a1, a2, a3, vb[0], vb[1]);
                MMA_F16(o[2 * fn2 + 1], a0, a1, a2, a3, vb[2], vb[3]);
            }
        }

        // prefetch kt+2 into stage (kt+2)%3 == (kt-1)%3 (safe: barrier above)
        if (kt + 2 < NT) load_kv(kt + 2, (kt + 2) % KVSTG);
    }

    const float inv0 = 1.f / l[0];
    const float inv1 = 1.f / l[1];
    const int row0 = q0 + m0 + gid;
#pragma unroll
    for (int d = 0; d < 8; d++) {
        const int col = d * 8 + tig * 2;
        *(__half2*)(Ob + (size_t)row0 * DMODEL + col) =
            __floats2half2_rn(o[d][0] * inv0, o[d][1] * inv0);
        *(__half2*)(Ob + (size_t)(row0 + 8) * DMODEL + col) =
            __floats2half2_rn(o[d][2] * inv1, o[d][3] * inv1);
    }
}

// ---------------------------------------------------------------------------
// y = LayerNorm(a + b) * gamma + beta; dual output (fp32 + fp16)
// ---------------------------------------------------------------------------
__global__ __launch_bounds__(256)
void add_ln2(const float* __restrict__ a, const float* __restrict__ b,
             const float* __restrict__ gamma, const float* __restrict__ beta,
             float* __restrict__ y, __half* __restrict__ yh)
{
    const int row = blockIdx.x;
    const int tid = threadIdx.x;
    __shared__ float rs[256], rq[256];

    float4 va = ((const float4*)(a + (size_t)row * DMODEL))[tid];
    float4 vb = ((const float4*)(b + (size_t)row * DMODEL))[tid];
    float s0 = va.x + vb.x, s1 = va.y + vb.y, s2 = va.z + vb.z, s3 = va.w + vb.w;

    rs[tid] = s0 + s1 + s2 + s3;
    rq[tid] = s0 * s0 + s1 * s1 + s2 * s2 + s3 * s3;
    __syncthreads();
#pragma unroll
    for (int off = 128; off > 0; off >>= 1) {
        if (tid < off) { rs[tid] += rs[tid + off]; rq[tid] += rq[tid + off]; }
        __syncthreads();
    }
    const float mu   = rs[0] * (1.f / DMODEL);
    const float var  = rq[0] * (1.f / DMODEL) - mu * mu;
    const float rinv = rsqrtf(var + 1e-5f);

    float4 g  = ((const float4*)gamma)[tid];
    float4 be = ((const float4*)beta)[tid];
    float4 out;
    out.x = (s0 - mu) * rinv * g.x + be.x;
    out.y = (s1 - mu) * rinv * g.y + be.y;
    out.z = (s2 - mu) * rinv * g.z + be.z;
    out.w = (s3 - mu) * rinv * g.w + be.w;
    ((float4*)(y + (size_t)row * DMODEL))[tid] = out;

    __half* hp = yh + (size_t)row * DMODEL + tid * 4;
    *(__half2*)(hp)     = __floats2half2_rn(out.x, out.y);
    *(__half2*)(hp + 2) = __floats2half2_rn(out.z, out.w);
}

// ---------------------------------------------------------------------------
// launch
// ---------------------------------------------------------------------------
extern "C" void kernel_launch(void* const* d_in, const int* in_sizes, int n_in,
                              void* d_out, int out_size)
{
    const float* x  = (const float*)d_in[0];
    const float* Wq = (const float*)d_in[1];
    const float* Wk = (const float*)d_in[2];
    const float* Wv = (const float*)d_in[3];
    const float* Wo = (const float*)d_in[4];
    const float* W1 = (const float*)d_in[5];
    const float* W2 = (const float*)d_in[6];
    const float* g1 = (const float*)d_in[7];
    const float* b1 = (const float*)d_in[8];
    const float* g2 = (const float*)d_in[9];
    const float* b2 = (const float*)d_in[10];
    float* out = (float*)d_out;

    __half *px, *pwq, *pwk, *pwv, *pwo, *pw1, *pw2;
    __half *pq, *pk, *pvt, *pattn, *px1h, *pff;
    float *pproj, *px1;
    cudaGetSymbolAddress((void**)&px,   hx);
    cudaGetSymbolAddress((void**)&pwq,  hWq);
    cudaGetSymbolAddress((void**)&pwk,  hWk);
    cudaGetSymbolAddress((void**)&pwv,  hWv);
    cudaGetSymbolAddress((void**)&pwo,  hWo);
    cudaGetSymbolAddress((void**)&pw1,  hW1);
    cudaGetSymbolAddress((void**)&pw2,  hW2);
    cudaGetSymbolAddress((void**)&pq,   hq);
    cudaGetSymbolAddress((void**)&pk,   hk);
    cudaGetSymbolAddress((void**)&pvt,  hvt);
    cudaGetSymbolAddress((void**)&pattn,hattn);
    cudaGetSymbolAddress((void**)&px1h, hx1);
    cudaGetSymbolAddress((void**)&pff,  hff);
    cudaGetSymbolAddress((void**)&pproj,g_proj);
    cudaGetSymbolAddress((void**)&px1,  g_x1);

    cudaFuncSetAttribute(gemm128<0>, cudaFuncAttributeMaxDynamicSharedMemorySize, GEMM_SMEM);
    cudaFuncSetAttribute(gemm128<3>, cudaFuncAttributeMaxDynamicSharedMemorySize, GEMM_SMEM);
    cudaFuncSetAttribute(gemm128<4>, cudaFuncAttributeMaxDynamicSharedMemorySize, GEMM_SMEM);
    cudaFuncSetAttribute(gemm_qkv,   cudaFuncAttributeMaxDynamicSharedMemorySize, GEMM_SMEM);
    cudaFuncSetAttribute(flash_h,    cudaFuncAttributeMaxDynamicSharedMemorySize, FLASHH_SMEM);

    dim3 blk(256);

    // fp32 -> fp16, single launch
    f2h_all<<<dim3(TOKENS * DMODEL / 1024, 7), blk>>>(
        x, px, Wq, pwq, Wk, pwk, Wv, pwv, Wo, pwo, W1, pw1, W2, pw2);

    // fused QKV projections (grid.x = 3 weights * 8 n-tiles)
    gemm_qkv<<<dim3(24, TOKENS / 128), blk, GEMM_SMEM>>>(
        px, pwq, pwk, pwv, pq, pk, pvt);

    // attention
    dim3 gattn(SEQ / 128, 2 * NHEADS);
    flash_h<<<gattn, blk, FLASHH_SMEM>>>(pq, pk, pvt, pattn);

    // output projection + residual + LN1
    gemm128<4><<<dim3(DMODEL / 128, TOKENS / 128), blk, GEMM_SMEM>>>(
        pattn, pwo, pproj, TOKENS, DMODEL, DMODEL);
    add_ln2<<<TOKENS, 256>>>(x, pproj, g1, b1, px1, px1h);

    // FF1 (+GELU), FF2, residual + LN2
    gemm128<3><<<dim3(DFF / 128, TOKENS / 128), blk, GEMM_SMEM>>>(
        px1h, pw1, pff, TOKENS, DFF, DMODEL);
    gemm128<4><<<dim3(DMODEL / 128, TOKENS / 128), blk, GEMM_SMEM>>>(
        pff, pw2, pproj, TOKENS, DMODEL, DFF);
    add_ln2<<<TOKENS, 256>>>(px1, pproj, g2, b2, out, px1h);
}